// round 15
// baseline (speedup 1.0000x reference)
#include <cuda_runtime.h>
#include <cuda_bf16.h>
#include <cstdint>
#include <cstddef>

// ---------------- problem constants ----------------
constexpr int N_INTn = 50000;
constexpr int D      = 128;
constexpr int DCn    = 64;
constexpr int E_INTn = 500000;
constexpr int E_Bn   = 20000;
constexpr int E_Cn   = 10000;
constexpr int NP_I   = 50048;   // 391*128
constexpr int NP_B   = 20096;   // 157*128
constexpr int NP_C   = 10112;   // 79*128
constexpr int KFE    = 704;     // featext K
constexpr int MAXD   = 64;      // CSR slots per node
constexpr int OVCAP  = E_INTn;  // overflow can never drop

// ---------------- fp32 scratch ----------------
__device__ float g_feat[N_INTn * 320];   // only cols [128,320) used now
__device__ float g_cntI[N_INTn], g_cntB[N_INTn], g_cntC[N_INTn];
__device__ int   g_cntIi[N_INTn];
__device__ int   g_csr[(size_t)N_INTn * MAXD];
__device__ int   g_ovfc;
__device__ int2  g_ovf[OVCAP];
__device__ float g_bOI[256], g_bOB[256], g_bOC[256];

// ---------------- bf16 hi/lo planes ----------------
__device__ __align__(16) __nv_bfloat16 g_xh[NP_I * 128],  g_xl[NP_I * 128];
__device__ __align__(16) __nv_bfloat16 g_xbh[NP_B * 128], g_xbl[NP_B * 128];
__device__ __align__(16) __nv_bfloat16 g_uh[NP_C * 64],   g_ul[NP_C * 64];
__device__ __align__(16) __nv_bfloat16 g_feh[(size_t)NP_I * KFE], g_fel[(size_t)NP_I * KFE];
__device__ __align__(16) __nv_bfloat16 g_aggh[NP_I * 128], g_aggl[NP_I * 128];
__device__ __align__(16) __nv_bfloat16 g_sbh[NP_B * 128],  g_sbl[NP_B * 128];
__device__ __align__(16) __nv_bfloat16 g_sch[NP_C * 128],  g_scl[NP_C * 128];
// weight planes
__device__ __align__(16) __nv_bfloat16 g_W1h[128 * KFE], g_W1l[128 * KFE];
__device__ __align__(16) __nv_bfloat16 g_WOIh[256 * 256], g_WOIl[256 * 256];
__device__ __align__(16) __nv_bfloat16 g_WB1h[128 * 128], g_WB1l[128 * 128];
__device__ __align__(16) __nv_bfloat16 g_WOBh[256 * 256], g_WOBl[256 * 256];
__device__ __align__(16) __nv_bfloat16 g_WC1h[128 * 64],  g_WC1l[128 * 64];
__device__ __align__(16) __nv_bfloat16 g_WOCh[256 * 192], g_WOCl[256 * 192];

// ---------------- PTX helpers ----------------
__device__ __forceinline__ uint32_t cvta_s(const void* p) {
    uint32_t a;
    asm("{ .reg .u64 t; cvta.to.shared.u64 t, %1; cvt.u32.u64 %0, t; }" : "=r"(a) : "l"(p));
    return a;
}
#define CPA16(dst, src) asm volatile("cp.async.cg.shared.global [%0], [%1], 16;" :: "r"(dst), "l"(src))
#define CPCOMMIT()      asm volatile("cp.async.commit_group;" ::: "memory")
#define CPWAIT1()       asm volatile("cp.async.wait_group 1;" ::: "memory")

#define LDSM4(r0, r1, r2, r3, a) \
    asm volatile("ldmatrix.sync.aligned.m8n8.x4.shared.b16 {%0,%1,%2,%3}, [%4];" \
                 : "=r"(r0), "=r"(r1), "=r"(r2), "=r"(r3) : "r"(a))

#define MMA16816(c, av, b0, b1) \
    asm volatile("mma.sync.aligned.m16n8k16.row.col.f32.bf16.bf16.f32 " \
                 "{%0,%1,%2,%3}, {%4,%5,%6,%7}, {%8,%9}, {%0,%1,%2,%3};" \
                 : "+f"((c)[0]), "+f"((c)[1]), "+f"((c)[2]), "+f"((c)[3]) \
                 : "r"((av)[0]), "r"((av)[1]), "r"((av)[2]), "r"((av)[3]), \
                   "r"(b0), "r"(b1))

__device__ __forceinline__ uint32_t pack_bf2(float a, float b) {
    __nv_bfloat162 t;
    t.x = __float2bfloat16_rn(a);
    t.y = __float2bfloat16_rn(b);
    return *reinterpret_cast<uint32_t*>(&t);
}
__device__ __forceinline__ uint32_t pack_lo2(float a, float b) {
    __nv_bfloat16 ha = __float2bfloat16_rn(a), hb = __float2bfloat16_rn(b);
    __nv_bfloat162 t;
    t.x = __float2bfloat16_rn(a - __bfloat162float(ha));
    t.y = __float2bfloat16_rn(b - __bfloat162float(hb));
    return *reinterpret_cast<uint32_t*>(&t);
}
__device__ __forceinline__ void split8(const float* v, uint4& H, uint4& L) {
    __nv_bfloat16 h[8], l[8];
    #pragma unroll
    for (int j = 0; j < 8; j++) {
        h[j] = __float2bfloat16_rn(v[j]);
        l[j] = __float2bfloat16_rn(v[j] - __bfloat162float(h[j]));
    }
    H = *reinterpret_cast<const uint4*>(h);
    L = *reinterpret_cast<const uint4*>(l);
}
__device__ __forceinline__ void split4(const float* v, uint2& H, uint2& L) {
    __nv_bfloat16 h[4], l[4];
    for (int j = 0; j < 4; j++) {
        h[j] = __float2bfloat16_rn(v[j]);
        l[j] = __float2bfloat16_rn(v[j] - __bfloat162float(h[j]));
    }
    H = *reinterpret_cast<const uint2*>(h);
    L = *reinterpret_cast<const uint2*>(l);
}
__device__ __forceinline__ void ld8(const float* p, float* v) {
    float4 a = ((const float4*)p)[0], b = ((const float4*)p)[1];
    v[0]=a.x; v[1]=a.y; v[2]=a.z; v[3]=a.w; v[4]=b.x; v[5]=b.y; v[6]=b.z; v[7]=b.w;
}
__device__ __forceinline__ void zero8(float* v) {
    for (int j = 0; j < 8; j++) v[j] = 0.f;
}

// ---------------- generic plane GEMM ----------------
constexpr int TILE_B  = 128 * 64;
constexpr int STAGE_B = 4 * TILE_B;
constexpr int SM_BIAS = 3 * STAGE_B;
constexpr int SM_TOT  = SM_BIAS + 3 * 128 * 4;

__device__ __forceinline__ void issue_tile(
    uint32_t sb, int stage, int kt,
    const __nv_bfloat16* A0h, const __nv_bfloat16* A0l, int K0,
    const __nv_bfloat16* A1h, const __nv_bfloat16* A1l, int K1,
    const __nv_bfloat16* Wh, const __nv_bfloat16* Wl, int Kt,
    int mbase, int nbase, int tid)
{
    int kc = kt << 5;
    const __nv_bfloat16 *ah, *al;
    int ld, ko;
    if (kc < K0) { ah = A0h; al = A0l; ld = K0; ko = kc; }
    else         { ah = A1h; al = A1l; ld = K1; ko = kc - K0; }
    uint32_t base = sb + stage * STAGE_B;
    #pragma unroll
    for (int r = 0; r < 2; r++) {
        int chunk = tid + r * 256;
        int row = chunk >> 2, c = chunk & 3;
        uint32_t sc = (uint32_t)(c ^ ((row >> 1) & 3));
        uint32_t off = row * 64 + sc * 16;
        size_t aoff = (size_t)(mbase + row) * ld + ko + c * 8;
        size_t woff = (size_t)(nbase + row) * Kt + kc + c * 8;
        CPA16(base + off,              ah + aoff);
        CPA16(base + TILE_B + off,     al + aoff);
        CPA16(base + 2 * TILE_B + off, Wh + woff);
        CPA16(base + 3 * TILE_B + off, Wl + woff);
    }
}

// mode 0: fp32 out C = acc + bias; mode 1: split planes (+bias); mode 2: AGG epilogue
__global__ void __launch_bounds__(256, 2) k_gemm(
    const __nv_bfloat16* __restrict__ A0h, const __nv_bfloat16* __restrict__ A0l, int K0,
    const __nv_bfloat16* __restrict__ A1h, const __nv_bfloat16* __restrict__ A1l, int K1,
    const __nv_bfloat16* __restrict__ Wh,  const __nv_bfloat16* __restrict__ Wl,
    const float* __restrict__ bias,
    float* __restrict__ C, int ldc, int M,
    __nv_bfloat16* __restrict__ Dh, __nv_bfloat16* __restrict__ Dl,
    int mode,
    const float* __restrict__ b1, const float* __restrict__ b2,
    const float* __restrict__ b3)
{
    extern __shared__ char smem[];
    uint32_t sb = cvta_s(smem);
    const int tid  = threadIdx.x;
    const int wid  = tid >> 5;
    const int lane = tid & 31;
    const int wm   = wid >> 1;
    const int wn   = wid & 1;
    const int mbase = blockIdx.x * 128;
    const int nbase = blockIdx.y * 128;
    const int Kt = K0 + K1;
    const int nk = Kt >> 5;

    float* bs1 = (float*)(smem + SM_BIAS);
    float* bs2 = bs1 + 128;
    float* bs3 = bs2 + 128;
    if (tid < 128) {
        if (mode == 2) {
            bs1[tid] = b1[tid]; bs2[tid] = b2[tid]; bs3[tid] = b3[tid];
        } else {
            bs1[tid] = bias ? bias[nbase + tid] : 0.f;
        }
    }

    const int hi = lane >> 4;
    const int jj = lane >> 3;
    const int a_row0 = wm * 32 + (lane & 15);
    const uint32_t xr_a = (uint32_t)((a_row0 >> 1) & 3);
    const uint32_t a_ro[2] = {(uint32_t)(a_row0 * 64), (uint32_t)((a_row0 + 16) * 64)};
    const int b_row0 = wn * 64 + ((jj >> 1) * 8) + (lane & 7);
    const uint32_t xr_b = (uint32_t)((b_row0 >> 1) & 3);
    const uint32_t b_ro = (uint32_t)(b_row0 * 64);
    const uint32_t b_ch = (uint32_t)(jj & 1);

    float acc[2][8][4];
    #pragma unroll
    for (int mt = 0; mt < 2; mt++)
        #pragma unroll
        for (int nt = 0; nt < 8; nt++)
            #pragma unroll
            for (int j = 0; j < 4; j++) acc[mt][nt][j] = 0.f;

    issue_tile(sb, 0, 0, A0h, A0l, K0, A1h, A1l, K1, Wh, Wl, Kt, mbase, nbase, tid);
    CPCOMMIT();
    if (nk > 1)
        issue_tile(sb, 1, 1, A0h, A0l, K0, A1h, A1l, K1, Wh, Wl, Kt, mbase, nbase, tid);
    CPCOMMIT();

    for (int kt = 0; kt < nk; kt++) {
        int stage = kt % 3;
        CPWAIT1();
        __syncthreads();
        // prefetch stage (kt+2)%3 EARLY: that buffer was consumed at kt-1 and
        // all warps passed the barrier above, so overwrite is safe; the loads
        // now overlap this iteration's entire MMA block.
        if (kt + 2 < nk)
            issue_tile(sb, (kt + 2) % 3, kt + 2, A0h, A0l, K0, A1h, A1l, K1,
                       Wh, Wl, Kt, mbase, nbase, tid);
        CPCOMMIT();
        uint32_t base = sb + stage * STAGE_B;
        #pragma unroll
        for (int s = 0; s < 2; s++) {
            uint32_t ca = ((uint32_t)(s * 2 + hi) ^ xr_a) * 16;
            uint32_t cb = ((uint32_t)(s * 2) + b_ch ^ xr_b) * 16;
            uint32_t ah[2][4], al[2][4];
            #pragma unroll
            for (int mt = 0; mt < 2; mt++) {
                uint32_t ad = base + a_ro[mt] + ca;
                LDSM4(ah[mt][0], ah[mt][1], ah[mt][2], ah[mt][3], ad);
                LDSM4(al[mt][0], al[mt][1], al[mt][2], al[mt][3], ad + TILE_B);
            }
            uint32_t bh[8][2], bl[8][2];
            #pragma unroll
            for (int g = 0; g < 4; g++) {
                uint32_t bd = base + 2 * TILE_B + b_ro + g * 1024 + cb;
                uint32_t r0, r1, r2, r3;
                LDSM4(r0, r1, r2, r3, bd);
                bh[g * 2][0] = r0; bh[g * 2][1] = r1;
                bh[g * 2 + 1][0] = r2; bh[g * 2 + 1][1] = r3;
                LDSM4(r0, r1, r2, r3, bd + TILE_B);
                bl[g * 2][0] = r0; bl[g * 2][1] = r1;
                bl[g * 2 + 1][0] = r2; bl[g * 2 + 1][1] = r3;
            }
            #pragma unroll
            for (int mt = 0; mt < 2; mt++)
                #pragma unroll
                for (int nt = 0; nt < 8; nt++) {
                    MMA16816(acc[mt][nt], ah[mt], bh[nt][0], bh[nt][1]);
                    MMA16816(acc[mt][nt], ah[mt], bl[nt][0], bl[nt][1]);
                    MMA16816(acc[mt][nt], al[mt], bh[nt][0], bh[nt][1]);
                }
        }
    }

    #pragma unroll
    for (int mt = 0; mt < 2; mt++) {
        int r0 = mbase + wm * 32 + mt * 16 + (lane >> 2);
        int r1 = r0 + 8;
        float ci0 = 0.f, cb0 = 0.f, cc0 = 0.f, inv0 = 1.f;
        float ci1 = 0.f, cb1 = 0.f, cc1 = 0.f, inv1 = 1.f;
        if (mode == 2) {
            if (r0 < N_INTn) {
                ci0 = g_cntI[r0]; cb0 = g_cntB[r0]; cc0 = g_cntC[r0];
                inv0 = 1.f / fmaxf(ci0 + cb0 + cc0, 1.f);
            }
            if (r1 < N_INTn) {
                ci1 = g_cntI[r1]; cb1 = g_cntB[r1]; cc1 = g_cntC[r1];
                inv1 = 1.f / fmaxf(ci1 + cb1 + cc1, 1.f);
            }
        }
        #pragma unroll
        for (int nt = 0; nt < 8; nt++) {
            int nl = wn * 64 + nt * 8 + (lane & 3) * 2;
            float v00 = acc[mt][nt][0], v01 = acc[mt][nt][1];
            float v10 = acc[mt][nt][2], v11 = acc[mt][nt][3];
            if (mode == 0) {
                float b0 = bs1[nl], b1v = bs1[nl + 1];
                if (r0 < M) {
                    float2 o = {v00 + b0, v01 + b1v};
                    *reinterpret_cast<float2*>(C + (size_t)r0 * ldc + nbase + nl) = o;
                }
                if (r1 < M) {
                    float2 o = {v10 + b0, v11 + b1v};
                    *reinterpret_cast<float2*>(C + (size_t)r1 * ldc + nbase + nl) = o;
                }
            } else if (mode == 1) {
                float b0 = bs1[nl], b1v = bs1[nl + 1];
                v00 += b0; v01 += b1v; v10 += b0; v11 += b1v;
                size_t i0 = (size_t)r0 * 128 + nbase + nl;
                size_t i1 = (size_t)r1 * 128 + nbase + nl;
                *reinterpret_cast<uint32_t*>(Dh + i0) = pack_bf2(v00, v01);
                *reinterpret_cast<uint32_t*>(Dl + i0) = pack_lo2(v00, v01);
                *reinterpret_cast<uint32_t*>(Dh + i1) = pack_bf2(v10, v11);
                *reinterpret_cast<uint32_t*>(Dl + i1) = pack_lo2(v10, v11);
            } else {
                float e0 = bs1[nl] , e1 = bs1[nl + 1];
                float f0 = bs2[nl] , f1 = bs2[nl + 1];
                float g0 = bs3[nl] , g1 = bs3[nl + 1];
                v00 = (v00 + ci0 * e0 + cb0 * f0 + cc0 * g0) * inv0;
                v01 = (v01 + ci0 * e1 + cb0 * f1 + cc0 * g1) * inv0;
                v10 = (v10 + ci1 * e0 + cb1 * f0 + cc1 * g0) * inv1;
                v11 = (v11 + ci1 * e1 + cb1 * f1 + cc1 * g1) * inv1;
                size_t i0 = (size_t)r0 * 128 + nbase + nl;
                size_t i1 = (size_t)r1 * 128 + nbase + nl;
                *reinterpret_cast<uint32_t*>(Dh + i0) = pack_bf2(v00, v01);
                *reinterpret_cast<uint32_t*>(Dl + i0) = pack_lo2(v00, v01);
                *reinterpret_cast<uint32_t*>(Dh + i1) = pack_bf2(v10, v11);
                *reinterpret_cast<uint32_t*>(Dl + i1) = pack_lo2(v10, v11);
            }
        }
    }
}

// ---------------- zero scratch (aggB/aggC cols + counters only) ----------------
__global__ void k_zero() {
    int idx = blockIdx.x * blockDim.x + threadIdx.x;
    int stride = gridDim.x * blockDim.x;
    float4 z = {0.f, 0.f, 0.f, 0.f};
    for (int i = idx; i < N_INTn * 48; i += stride) {
        int m = i / 48, c = i % 48;
        ((float4*)(g_feat + (size_t)m * 320 + 128))[c] = z;
    }
    for (int i = idx; i < N_INTn; i += stride) {
        g_cntIi[i] = 0; g_cntB[i] = 0.f; g_cntC[i] = 0.f;
    }
    if (idx == 0) g_ovfc = 0;
}

// ---------------- interior: bucket then gather (planes written directly) ----------------
__global__ void k_reorder(const int* __restrict__ ei) {
    int idx = blockIdx.x * blockDim.x + threadIdx.x;
    if (idx >= E_INTn) return;
    int s = ei[idx];
    int t = ei[E_INTn + idx];
    int p = atomicAdd(&g_cntIi[t], 1);
    if (p < MAXD) {
        g_csr[(size_t)t * MAXD + p] = s;
    } else {
        int o = atomicAdd(&g_ovfc, 1);
        g_ovf[o] = make_int2(s, t);
    }
}

__global__ void k_gather(const float* __restrict__ x) {
    int n = (blockIdx.x * blockDim.x + threadIdx.x) >> 5;
    int lane = threadIdx.x & 31;
    if (n >= NP_I) return;
    size_t pb = (size_t)n * KFE + lane * 4;
    if (n >= N_INTn) {
        uint2 z = {0u, 0u};
        *(uint2*)(g_feh + pb) = z;       *(uint2*)(g_fel + pb) = z;
        *(uint2*)(g_feh + pb + 320) = z; *(uint2*)(g_fel + pb + 320) = z;
        return;
    }
    int deg = g_cntIi[n];
    int d = min(deg, MAXD);
    const int* cs = g_csr + (size_t)n * MAXD;
    float4 acc = {0.f, 0.f, 0.f, 0.f};
    int e = 0;
    for (; e + 4 <= d; e += 4) {
        int s0 = cs[e], s1 = cs[e + 1], s2 = cs[e + 2], s3 = cs[e + 3];
        float4 v0 = ((const float4*)(x + (size_t)s0 * D))[lane];
        float4 v1 = ((const float4*)(x + (size_t)s1 * D))[lane];
        float4 v2 = ((const float4*)(x + (size_t)s2 * D))[lane];
        float4 v3 = ((const float4*)(x + (size_t)s3 * D))[lane];
        acc.x += v0.x + v1.x + v2.x + v3.x;
        acc.y += v0.y + v1.y + v2.y + v3.y;
        acc.z += v0.z + v1.z + v2.z + v3.z;
        acc.w += v0.w + v1.w + v2.w + v3.w;
    }
    for (; e < d; e++) {
        int s = cs[e];
        float4 v = ((const float4*)(x + (size_t)s * D))[lane];
        acc.x += v.x; acc.y += v.y; acc.z += v.z; acc.w += v.w;
    }
    if (deg > MAXD) {
        int no = g_ovfc;
        for (int o = 0; o < no; o++) {
            int2 p = g_ovf[o];
            if (p.y == n) {
                float4 v = ((const float4*)(x + (size_t)p.x * D))[lane];
                acc.x += v.x; acc.y += v.y; acc.z += v.z; acc.w += v.w;
            }
        }
    }
    float av[4] = {acc.x, acc.y, acc.z, acc.w};
    uint2 H, L;
    split4(av, H, L);
    *(uint2*)(g_feh + pb) = H;
    *(uint2*)(g_fel + pb) = L;
    float ci = (float)deg;
    float4 xv = ((const float4*)(x + (size_t)n * D))[lane];
    float sv[4] = {ci * xv.x, ci * xv.y, ci * xv.z, ci * xv.w};
    split4(sv, H, L);
    *(uint2*)(g_feh + pb + 320) = H;
    *(uint2*)(g_fel + pb + 320) = L;
    if (lane == 0) g_cntI[n] = ci;
}

// ---------------- boundary/control scatter (red-based) ----------------
__device__ __forceinline__ void red4(float* p, float4 v) {
    asm volatile("red.global.add.v4.f32 [%0], {%1,%2,%3,%4};"
                 :: "l"(p), "f"(v.x), "f"(v.y), "f"(v.z), "f"(v.w) : "memory");
}

constexpr int WB_W = E_Bn / 4;
constexpr int WC_W = WB_W + E_Cn / 4;

__global__ void k_scatterBC(const int* __restrict__ eiB, const int* __restrict__ eiC,
                            const float* __restrict__ xb, const float* __restrict__ u)
{
    int w = (blockIdx.x * blockDim.x + threadIdx.x) >> 5;
    int lane = threadIdx.x & 31;
    if (w < WB_W) {
        int e0 = w * 4;
        int t[4];
        #pragma unroll
        for (int j = 0; j < 4; j++) t[j] = eiB[E_Bn + e0 + j];
        float4 v[4];
        #pragma unroll
        for (int j = 0; j < 4; j++)
            v[j] = ((const float4*)(xb + (size_t)(e0 + j) * D))[lane];
        #pragma unroll
        for (int j = 0; j < 4; j++)
            red4(g_feat + (size_t)t[j] * 320 + 128 + lane * 4, v[j]);
        if (lane == 0) {
            #pragma unroll
            for (int j = 0; j < 4; j++) atomicAdd(&g_cntB[t[j]], 1.0f);
        }
    } else if (w < WC_W) {
        int e0 = (w - WB_W) * 4;
        int t[4];
        #pragma unroll
        for (int j = 0; j < 4; j++) t[j] = eiC[E_Cn + e0 + j];
        if (lane < 16) {
            float4 v[4];
            #pragma unroll
            for (int j = 0; j < 4; j++)
                v[j] = ((const float4*)(u + (size_t)(e0 + j) * DCn))[lane];
            #pragma unroll
            for (int j = 0; j < 4; j++)
                red4(g_feat + (size_t)t[j] * 320 + 256 + lane * 4, v[j]);
        }
        if (lane == 0) {
            #pragma unroll
            for (int j = 0; j < 4; j++) atomicAdd(&g_cntC[t[j]], 1.0f);
        }
    }
}

// ---------------- prep_rest: vectorized (8 elems / thread) ----------------
constexpr int V_W1  = 128 * 88;
constexpr int V_WOI = V_W1 + 256 * 32;
constexpr int V_WB1 = V_WOI + 128 * 16;
constexpr int V_WOB = V_WB1 + 256 * 32;
constexpr int V_WC1 = V_WOB + 128 * 8;
constexpr int V_WOC = V_WC1 + 256 * 24;
constexpr int V_B   = V_WOC + 96;
constexpr int V_X   = V_B + NP_I * 16;
constexpr int V_XB  = V_X + NP_B * 16;
constexpr int V_U   = V_XB + NP_C * 8;

__global__ void k_prep_rest(
    const float* __restrict__ x, const float* __restrict__ xb, const float* __restrict__ u,
    const float* __restrict__ Wii, const float* __restrict__ Wbi, const float* __restrict__ Wci,
    const float* __restrict__ Wbb, const float* __restrict__ Wcc,
    const float* __restrict__ Wis, const float* __restrict__ Wim,
    const float* __restrict__ Wbs, const float* __restrict__ Wbm,
    const float* __restrict__ Wcs, const float* __restrict__ Wcm,
    const float* __restrict__ bis, const float* __restrict__ bim,
    const float* __restrict__ bbs, const float* __restrict__ bbm,
    const float* __restrict__ bcs, const float* __restrict__ bcm)
{
    int idx = blockIdx.x * blockDim.x + threadIdx.x;
    float v[8];
    uint4 H, L;
    if (idx < V_W1) {
        int j = idx / 88, k0 = (idx % 88) * 8;
        const float* src;
        if (k0 < 128)      src = Wii + j * 256 + k0;
        else if (k0 < 256) src = Wbi + j * 256 + (k0 - 128);
        else if (k0 < 320) src = Wci + j * 192 + (k0 - 256);
        else if (k0 < 448) src = Wii + j * 256 + 128 + (k0 - 320);
        else if (k0 < 576) src = Wbi + j * 256 + 128 + (k0 - 448);
        else               src = Wci + j * 192 + 64 + (k0 - 576);
        ld8(src, v);
        split8(v, H, L);
        size_t o = (size_t)j * KFE + k0;
        *(uint4*)(g_W1h + o) = H; *(uint4*)(g_W1l + o) = L;
        return;
    }
    if (idx < V_WOI) {
        int i = idx - V_W1;
        int j = i / 32, k0 = (i % 32) * 8;
        const float* src = (k0 < 128) ? Wis + j * 128 + k0 : Wim + j * 128 + (k0 - 128);
        ld8(src, v); split8(v, H, L);
        size_t o = (size_t)j * 256 + k0;
        *(uint4*)(g_WOIh + o) = H; *(uint4*)(g_WOIl + o) = L;
        return;
    }
    if (idx < V_WB1) {
        int i = idx - V_WOI;
        int j = i / 16, k0 = (i % 16) * 8;
        float a[8], b[8];
        ld8(Wbb + j * 256 + k0, a); ld8(Wbb + j * 256 + 128 + k0, b);
        for (int t = 0; t < 8; t++) v[t] = a[t] + b[t];
        split8(v, H, L);
        size_t o = (size_t)j * 128 + k0;
        *(uint4*)(g_WB1h + o) = H; *(uint4*)(g_WB1l + o) = L;
        return;
    }
    if (idx < V_WOB) {
        int i = idx - V_WB1;
        int j = i / 32, k0 = (i % 32) * 8;
        const float* src = (k0 < 128) ? Wbs + j * 128 + k0 : Wbm + j * 128 + (k0 - 128);
        ld8(src, v); split8(v, H, L);
        size_t o = (size_t)j * 256 + k0;
        *(uint4*)(g_WOBh + o) = H; *(uint4*)(g_WOBl + o) = L;
        return;
    }
    if (idx < V_WC1) {
        int i = idx - V_WOB;
        int j = i / 8, k0 = (i % 8) * 8;
        float a[8], b[8];
        ld8(Wcc + j * 128 + k0, a); ld8(Wcc + j * 128 + 64 + k0, b);
        for (int t = 0; t < 8; t++) v[t] = a[t] + b[t];
        split8(v, H, L);
        size_t o = (size_t)j * 64 + k0;
        *(uint4*)(g_WC1h + o) = H; *(uint4*)(g_WC1l + o) = L;
        return;
    }
    if (idx < V_WOC) {
        int i = idx - V_WC1;
        int j = i / 24, k0 = (i % 24) * 8;
        const float* src = (k0 < 64) ? Wcs + j * 64 + k0 : Wcm + j * 128 + (k0 - 64);
        ld8(src, v); split8(v, H, L);
        size_t o = (size_t)j * 192 + k0;
        *(uint4*)(g_WOCh + o) = H; *(uint4*)(g_WOCl + o) = L;
        return;
    }
    if (idx < V_B) {
        int i = idx - V_WOC;
        int which = i / 32, c0 = (i % 32) * 8;
        const float *a, *b;
        float* dst;
        if (which == 0) { a = bis; b = bim; dst = g_bOI; }
        else if (which == 1) { a = bbs; b = bbm; dst = g_bOB; }
        else { a = bcs; b = bcm; dst = g_bOC; }
        float av[8], bv[8];
        ld8(a + c0, av); ld8(b + c0, bv);
        float4 o0, o1;
        o0.x = av[0] + bv[0]; o0.y = av[1] + bv[1]; o0.z = av[2] + bv[2]; o0.w = av[3] + bv[3];
        o1.x = av[4] + bv[4]; o1.y = av[5] + bv[5]; o1.z = av[6] + bv[6]; o1.w = av[7] + bv[7];
        ((float4*)(dst + c0))[0] = o0; ((float4*)(dst + c0))[1] = o1;
        return;
    }
    if (idx < V_X) {
        int i = idx - V_B;
        int m = i >> 4, c8 = (i & 15) * 8;
        if (m < N_INTn) ld8(x + (size_t)m * 128 + c8, v);
        else zero8(v);
        split8(v, H, L);
        size_t o = (size_t)m * 128 + c8;
        *(uint4*)(g_xh + o) = H; *(uint4*)(g_xl + o) = L;
        return;
    }
    if (idx < V_XB) {
        int i = idx - V_X;
        int m = i >> 4, c8 = (i & 15) * 8;
        if (m < E_Bn) ld8(xb + (size_t)m * 128 + c8, v);
        else zero8(v);
        split8(v, H, L);
        size_t o = (size_t)m * 128 + c8;
        *(uint4*)(g_xbh + o) = H; *(uint4*)(g_xbl + o) = L;
        return;
    }
    if (idx < V_U) {
        int i = idx - V_XB;
        int m = i >> 3, c8 = (i & 7) * 8;
        if (m < E_Cn) ld8(u + (size_t)m * 64 + c8, v);
        else zero8(v);
        split8(v, H, L);
        size_t o = (size_t)m * 64 + c8;
        *(uint4*)(g_uh + o) = H; *(uint4*)(g_ul + o) = L;
        return;
    }
}

// ---- prep_feat: only aggB/aggC cols + cb/cc-scaled x (gather owns the rest) ----
constexpr int PF_A   = NP_I * 24;
constexpr int PF_TOT = PF_A + NP_I * 16;

__global__ void k_prep_feat(const float* __restrict__ x)
{
    int idx = blockIdx.x * blockDim.x + threadIdx.x;
    if (idx < PF_A) {
        int m = idx / 24;
        int c8 = (idx % 24) * 8;
        float v[8];
        if (m < N_INTn) ld8(g_feat + (size_t)m * 320 + 128 + c8, v);
        else zero8(v);
        uint4 H, L;
        split8(v, H, L);
        *reinterpret_cast<uint4*>(g_feh + (size_t)m * KFE + 128 + c8) = H;
        *reinterpret_cast<uint4*>(g_fel + (size_t)m * KFE + 128 + c8) = L;
        return;
    }
    idx -= PF_A;
    if (idx < NP_I * 16) {
        int m = idx >> 4;
        int c8 = (idx & 15) * 8;
        float xv[8];
        float cb = 0.f, cc = 0.f;
        if (m < N_INTn) {
            ld8(x + (size_t)m * 128 + c8, xv);
            cb = g_cntB[m]; cc = g_cntC[m];
        } else {
            zero8(xv);
        }
        size_t base = (size_t)m * KFE;
        float sv[8];
        uint4 H, L;
        for (int j = 0; j < 8; j++) sv[j] = cb * xv[j];
        split8(sv, H, L);
        *reinterpret_cast<uint4*>(g_feh + base + 448 + c8) = H;
        *reinterpret_cast<uint4*>(g_fel + base + 448 + c8) = L;
        for (int j = 0; j < 8; j++) sv[j] = cc * xv[j];
        split8(sv, H, L);
        *reinterpret_cast<uint4*>(g_feh + base + 576 + c8) = H;
        *reinterpret_cast<uint4*>(g_fel + base + 576 + c8) = L;
        return;
    }
}

// ---------------- launch ----------------
static void* symv(const void* s) { void* p = nullptr; cudaGetSymbolAddress(&p, s); return p; }

extern "C" void kernel_launch(void* const* d_in, const int* in_sizes, int n_in,
                              void* d_out, int out_size) {
    const float* x   = (const float*)d_in[0];
    const float* xb  = (const float*)d_in[1];
    const float* u   = (const float*)d_in[2];
    const int*   eiI = (const int*)d_in[3];
    const int*   eiB = (const int*)d_in[4];
    const int*   eiC = (const int*)d_in[5];
    const float* Wii = (const float*)d_in[8];
    const float* bii = (const float*)d_in[9];
    const float* Wbi = (const float*)d_in[10];
    const float* bbi = (const float*)d_in[11];
    const float* Wci = (const float*)d_in[12];
    const float* bci = (const float*)d_in[13];
    const float* Wbb = (const float*)d_in[14];
    const float* bbb = (const float*)d_in[15];
    const float* Wcc = (const float*)d_in[16];
    const float* bcc = (const float*)d_in[17];
    const float* Wim = (const float*)d_in[18];
    const float* bim = (const float*)d_in[19];
    const float* Wis = (const float*)d_in[20];
    const float* bis = (const float*)d_in[21];
    const float* Wbm = (const float*)d_in[22];
    const float* bbm = (const float*)d_in[23];
    const float* Wbs = (const float*)d_in[24];
    const float* bbs = (const float*)d_in[25];
    const float* Wcm = (const float*)d_in[26];
    const float* bcm = (const float*)d_in[27];
    const float* Wcs = (const float*)d_in[28];
    const float* bcs = (const float*)d_in[29];
    float* out = (float*)d_out;

    auto bfp = [](const void* s) { return (const __nv_bfloat16*)symv(s); };
    auto bfw = [](const void* s) { return (__nv_bfloat16*)symv(s); };

    const __nv_bfloat16 *pxh = bfp(g_xh), *pxl = bfp(g_xl);
    const __nv_bfloat16 *pxbh = bfp(g_xbh), *pxbl = bfp(g_xbl);
    const __nv_bfloat16 *puh = bfp(g_uh), *pul = bfp(g_ul);
    const __nv_bfloat16 *pfeh = bfp(g_feh), *pfel = bfp(g_fel);
    __nv_bfloat16 *paggh = bfw(g_aggh), *paggl = bfw(g_aggl);
    __nv_bfloat16 *psbh = bfw(g_sbh), *psbl = bfw(g_sbl);
    __nv_bfloat16 *psch = bfw(g_sch), *pscl = bfw(g_scl);
    const __nv_bfloat16 *pW1h = bfp(g_W1h), *pW1l = bfp(g_W1l);
    const __nv_bfloat16 *pWOIh = bfp(g_WOIh), *pWOIl = bfp(g_WOIl);
    const __nv_bfloat16 *pWB1h = bfp(g_WB1h), *pWB1l = bfp(g_WB1l);
    const __nv_bfloat16 *pWOBh = bfp(g_WOBh), *pWOBl = bfp(g_WOBl);
    const __nv_bfloat16 *pWC1h = bfp(g_WC1h), *pWC1l = bfp(g_WC1l);
    const __nv_bfloat16 *pWOCh = bfp(g_WOCh), *pWOCl = bfp(g_WOCl);
    const float *pbOI = (const float*)symv(g_bOI);
    const float *pbOB = (const float*)symv(g_bOB);
    const float *pbOC = (const float*)symv(g_bOC);

    static cudaStream_t s1 = nullptr;
    static cudaEvent_t evF = nullptr, evZ = nullptr, evR = nullptr,
                       evS = nullptr, evJ = nullptr;
    if (s1 == nullptr) {
        cudaStreamCreateWithFlags(&s1, cudaStreamNonBlocking);
        cudaEventCreateWithFlags(&evF, cudaEventDisableTiming);
        cudaEventCreateWithFlags(&evZ, cudaEventDisableTiming);
        cudaEventCreateWithFlags(&evR, cudaEventDisableTiming);
        cudaEventCreateWithFlags(&evS, cudaEventDisableTiming);
        cudaEventCreateWithFlags(&evJ, cudaEventDisableTiming);
        cudaFuncSetAttribute(k_gemm, cudaFuncAttributeMaxDynamicSharedMemorySize, SM_TOT);
    }

    // fork
    cudaEventRecord(evF, 0);
    cudaStreamWaitEvent(s1, evF, 0);

    // ---- s0: zero first ----
    k_zero<<<1024, 256>>>();
    cudaEventRecord(evZ, 0);

    // ---- s1: scatterBC FIRST (only needs zero), then prep_rest + B/C chain ----
    cudaStreamWaitEvent(s1, evZ, 0);
    k_scatterBC<<<(WC_W * 32 + 255) / 256, 256, 0, s1>>>(eiB, eiC, xb, u);
    cudaEventRecord(evS, s1);
    k_prep_rest<<<(V_U + 255) / 256, 256, 0, s1>>>(
        x, xb, u, Wii, Wbi, Wci, Wbb, Wcc, Wis, Wim, Wbs, Wbm, Wcs, Wcm,
        bis, bim, bbs, bbm, bcs, bcm);
    cudaEventRecord(evR, s1);
    // SB = xb @ WB1^T + bbb -> planes
    k_gemm<<<dim3(157, 1), 256, SM_TOT, s1>>>(
        pxbh, pxbl, 128, nullptr, nullptr, 0, pWB1h, pWB1l,
        bbb, nullptr, 0, 0, psbh, psbl, 1, nullptr, nullptr, nullptr);
    // OUT-B = [xb | SB] @ WOB^T + bOB
    k_gemm<<<dim3(157, 2), 256, SM_TOT, s1>>>(
        pxbh, pxbl, 128, psbh, psbl, 128, pWOBh, pWOBl,
        pbOB, out + (size_t)N_INTn * 256, 256, E_Bn, nullptr, nullptr, 0,
        nullptr, nullptr, nullptr);
    // SC = u @ WC1^T + bcc -> planes
    k_gemm<<<dim3(79, 1), 256, SM_TOT, s1>>>(
        puh, pul, 64, nullptr, nullptr, 0, pWC1h, pWC1l,
        bcc, nullptr, 0, 0, psch, pscl, 1, nullptr, nullptr, nullptr);
    // OUT-C = [u | SC] @ WOC^T + bOC
    k_gemm<<<dim3(79, 2), 256, SM_TOT, s1>>>(
        puh, pul, 64, psch, pscl, 128, pWOCh, pWOCl,
        pbOC, out + (size_t)(N_INTn + E_Bn) * 256, 256, E_Cn, nullptr, nullptr, 0,
        nullptr, nullptr, nullptr);
    cudaEventRecord(evJ, s1);

    // ---- s0: interior chain ----
    k_reorder<<<(E_INTn + 255) / 256, 256>>>(eiI);
    k_gather<<<(NP_I * 32 + 255) / 256, 256>>>(x);
    cudaStreamWaitEvent(0, evS, 0);   // aggB/aggC + counts ready (early now)
    k_prep_feat<<<(PF_TOT + 255) / 256, 256>>>(x);

    cudaStreamWaitEvent(0, evR, 0);   // W1 + x planes ready
    // AGG = featext @ W1ext^T (K=704); epilogue: counts + msg biases -> planes
    k_gemm<<<dim3(391, 1), 256, SM_TOT>>>(
        pfeh, pfel, KFE, nullptr, nullptr, 0, pW1h, pW1l,
        nullptr, nullptr, 0, 0, paggh, paggl, 2, bii, bbi, bci);
    // OUT-I = [x | AGG] @ WOI^T + bOI
    k_gemm<<<dim3(391, 2), 256, SM_TOT>>>(
        pxh, pxl, 128, paggh, paggl, 128, pWOIh, pWOIl,
        pbOI, out, 256, N_INTn, nullptr, nullptr, 0, nullptr, nullptr, nullptr);

    // join
    cudaStreamWaitEvent(0, evJ, 0);
}

// round 16
// speedup vs baseline: 1.0349x; 1.0349x over previous
#include <cuda_runtime.h>
#include <cuda_bf16.h>
#include <cstdint>
#include <cstddef>

// ---------------- problem constants ----------------
constexpr int N_INTn = 50000;
constexpr int D      = 128;
constexpr int DCn    = 64;
constexpr int E_INTn = 500000;
constexpr int E_Bn   = 20000;
constexpr int E_Cn   = 10000;
constexpr int NP_I   = 50048;   // 391*128
constexpr int NP_B   = 20096;   // 157*128
constexpr int NP_C   = 10112;   // 79*128
constexpr int KFE    = 704;     // featext K
constexpr int MAXD   = 64;      // interior CSR slots per node
constexpr int MAXB   = 16;      // boundary CSR slots per node
constexpr int MAXC   = 16;      // control CSR slots per node

// ---------------- scratch ----------------
__device__ float g_cntI[N_INTn], g_cntB[N_INTn], g_cntC[N_INTn];
__device__ int   g_cntIi[N_INTn], g_cntBi[N_INTn], g_cntCi[N_INTn];
__device__ int   g_csr[(size_t)N_INTn * MAXD];
__device__ int   g_csrB[(size_t)N_INTn * MAXB];
__device__ int   g_csrC[(size_t)N_INTn * MAXC];
__device__ int   g_ovfc, g_ovfcB, g_ovfcC;
__device__ int2  g_ovf[E_INTn];
__device__ int2  g_ovfB[E_Bn];
__device__ int2  g_ovfC[E_Cn];
__device__ float g_bOI[256], g_bOB[256], g_bOC[256];

// ---------------- bf16 hi/lo planes ----------------
__device__ __align__(16) __nv_bfloat16 g_xh[NP_I * 128],  g_xl[NP_I * 128];
__device__ __align__(16) __nv_bfloat16 g_xbh[NP_B * 128], g_xbl[NP_B * 128];
__device__ __align__(16) __nv_bfloat16 g_uh[NP_C * 64],   g_ul[NP_C * 64];
__device__ __align__(16) __nv_bfloat16 g_feh[(size_t)NP_I * KFE], g_fel[(size_t)NP_I * KFE];
__device__ __align__(16) __nv_bfloat16 g_aggh[NP_I * 128], g_aggl[NP_I * 128];
__device__ __align__(16) __nv_bfloat16 g_sbh[NP_B * 128],  g_sbl[NP_B * 128];
__device__ __align__(16) __nv_bfloat16 g_sch[NP_C * 128],  g_scl[NP_C * 128];
// weight planes
__device__ __align__(16) __nv_bfloat16 g_W1h[128 * KFE], g_W1l[128 * KFE];
__device__ __align__(16) __nv_bfloat16 g_WOIh[256 * 256], g_WOIl[256 * 256];
__device__ __align__(16) __nv_bfloat16 g_WB1h[128 * 128], g_WB1l[128 * 128];
__device__ __align__(16) __nv_bfloat16 g_WOBh[256 * 256], g_WOBl[256 * 256];
__device__ __align__(16) __nv_bfloat16 g_WC1h[128 * 64],  g_WC1l[128 * 64];
__device__ __align__(16) __nv_bfloat16 g_WOCh[256 * 192], g_WOCl[256 * 192];

// ---------------- PTX helpers ----------------
__device__ __forceinline__ uint32_t cvta_s(const void* p) {
    uint32_t a;
    asm("{ .reg .u64 t; cvta.to.shared.u64 t, %1; cvt.u32.u64 %0, t; }" : "=r"(a) : "l"(p));
    return a;
}
#define CPA16(dst, src) asm volatile("cp.async.cg.shared.global [%0], [%1], 16;" :: "r"(dst), "l"(src))
#define CPCOMMIT()      asm volatile("cp.async.commit_group;" ::: "memory")
#define CPWAIT1()       asm volatile("cp.async.wait_group 1;" ::: "memory")

#define LDSM4(r0, r1, r2, r3, a) \
    asm volatile("ldmatrix.sync.aligned.m8n8.x4.shared.b16 {%0,%1,%2,%3}, [%4];" \
                 : "=r"(r0), "=r"(r1), "=r"(r2), "=r"(r3) : "r"(a))

#define MMA16816(c, av, b0, b1) \
    asm volatile("mma.sync.aligned.m16n8k16.row.col.f32.bf16.bf16.f32 " \
                 "{%0,%1,%2,%3}, {%4,%5,%6,%7}, {%8,%9}, {%0,%1,%2,%3};" \
                 : "+f"((c)[0]), "+f"((c)[1]), "+f"((c)[2]), "+f"((c)[3]) \
                 : "r"((av)[0]), "r"((av)[1]), "r"((av)[2]), "r"((av)[3]), \
                   "r"(b0), "r"(b1))

__device__ __forceinline__ uint32_t pack_bf2(float a, float b) {
    __nv_bfloat162 t;
    t.x = __float2bfloat16_rn(a);
    t.y = __float2bfloat16_rn(b);
    return *reinterpret_cast<uint32_t*>(&t);
}
__device__ __forceinline__ uint32_t pack_lo2(float a, float b) {
    __nv_bfloat16 ha = __float2bfloat16_rn(a), hb = __float2bfloat16_rn(b);
    __nv_bfloat162 t;
    t.x = __float2bfloat16_rn(a - __bfloat162float(ha));
    t.y = __float2bfloat16_rn(b - __bfloat162float(hb));
    return *reinterpret_cast<uint32_t*>(&t);
}
__device__ __forceinline__ void split8(const float* v, uint4& H, uint4& L) {
    __nv_bfloat16 h[8], l[8];
    #pragma unroll
    for (int j = 0; j < 8; j++) {
        h[j] = __float2bfloat16_rn(v[j]);
        l[j] = __float2bfloat16_rn(v[j] - __bfloat162float(h[j]));
    }
    H = *reinterpret_cast<const uint4*>(h);
    L = *reinterpret_cast<const uint4*>(l);
}
__device__ __forceinline__ void split4(const float* v, uint2& H, uint2& L) {
    __nv_bfloat16 h[4], l[4];
    for (int j = 0; j < 4; j++) {
        h[j] = __float2bfloat16_rn(v[j]);
        l[j] = __float2bfloat16_rn(v[j] - __bfloat162float(h[j]));
    }
    H = *reinterpret_cast<const uint2*>(h);
    L = *reinterpret_cast<const uint2*>(l);
}
__device__ __forceinline__ void ld8(const float* p, float* v) {
    float4 a = ((const float4*)p)[0], b = ((const float4*)p)[1];
    v[0]=a.x; v[1]=a.y; v[2]=a.z; v[3]=a.w; v[4]=b.x; v[5]=b.y; v[6]=b.z; v[7]=b.w;
}
__device__ __forceinline__ void zero8(float* v) {
    for (int j = 0; j < 8; j++) v[j] = 0.f;
}

// ---------------- generic plane GEMM (R14 structure, unchanged) ----------------
constexpr int TILE_B  = 128 * 64;
constexpr int STAGE_B = 4 * TILE_B;
constexpr int SM_BIAS = 3 * STAGE_B;
constexpr int SM_TOT  = SM_BIAS + 3 * 128 * 4;

__device__ __forceinline__ void issue_tile(
    uint32_t sb, int stage, int kt,
    const __nv_bfloat16* A0h, const __nv_bfloat16* A0l, int K0,
    const __nv_bfloat16* A1h, const __nv_bfloat16* A1l, int K1,
    const __nv_bfloat16* Wh, const __nv_bfloat16* Wl, int Kt,
    int mbase, int nbase, int tid)
{
    int kc = kt << 5;
    const __nv_bfloat16 *ah, *al;
    int ld, ko;
    if (kc < K0) { ah = A0h; al = A0l; ld = K0; ko = kc; }
    else         { ah = A1h; al = A1l; ld = K1; ko = kc - K0; }
    uint32_t base = sb + stage * STAGE_B;
    #pragma unroll
    for (int r = 0; r < 2; r++) {
        int chunk = tid + r * 256;
        int row = chunk >> 2, c = chunk & 3;
        uint32_t sc = (uint32_t)(c ^ ((row >> 1) & 3));
        uint32_t off = row * 64 + sc * 16;
        size_t aoff = (size_t)(mbase + row) * ld + ko + c * 8;
        size_t woff = (size_t)(nbase + row) * Kt + kc + c * 8;
        CPA16(base + off,              ah + aoff);
        CPA16(base + TILE_B + off,     al + aoff);
        CPA16(base + 2 * TILE_B + off, Wh + woff);
        CPA16(base + 3 * TILE_B + off, Wl + woff);
    }
}

// mode 0: fp32 out C = acc + bias; mode 1: split planes (+bias); mode 2: AGG epilogue
__global__ void __launch_bounds__(256, 2) k_gemm(
    const __nv_bfloat16* __restrict__ A0h, const __nv_bfloat16* __restrict__ A0l, int K0,
    const __nv_bfloat16* __restrict__ A1h, const __nv_bfloat16* __restrict__ A1l, int K1,
    const __nv_bfloat16* __restrict__ Wh,  const __nv_bfloat16* __restrict__ Wl,
    const float* __restrict__ bias,
    float* __restrict__ C, int ldc, int M,
    __nv_bfloat16* __restrict__ Dh, __nv_bfloat16* __restrict__ Dl,
    int mode,
    const float* __restrict__ b1, const float* __restrict__ b2,
    const float* __restrict__ b3)
{
    extern __shared__ char smem[];
    uint32_t sb = cvta_s(smem);
    const int tid  = threadIdx.x;
    const int wid  = tid >> 5;
    const int lane = tid & 31;
    const int wm   = wid >> 1;
    const int wn   = wid & 1;
    const int mbase = blockIdx.x * 128;
    const int nbase = blockIdx.y * 128;
    const int Kt = K0 + K1;
    const int nk = Kt >> 5;

    float* bs1 = (float*)(smem + SM_BIAS);
    float* bs2 = bs1 + 128;
    float* bs3 = bs2 + 128;
    if (tid < 128) {
        if (mode == 2) {
            bs1[tid] = b1[tid]; bs2[tid] = b2[tid]; bs3[tid] = b3[tid];
        } else {
            bs1[tid] = bias ? bias[nbase + tid] : 0.f;
        }
    }

    const int hi = lane >> 4;
    const int jj = lane >> 3;
    const int a_row0 = wm * 32 + (lane & 15);
    const uint32_t xr_a = (uint32_t)((a_row0 >> 1) & 3);
    const uint32_t a_ro[2] = {(uint32_t)(a_row0 * 64), (uint32_t)((a_row0 + 16) * 64)};
    const int b_row0 = wn * 64 + ((jj >> 1) * 8) + (lane & 7);
    const uint32_t xr_b = (uint32_t)((b_row0 >> 1) & 3);
    const uint32_t b_ro = (uint32_t)(b_row0 * 64);
    const uint32_t b_ch = (uint32_t)(jj & 1);

    float acc[2][8][4];
    #pragma unroll
    for (int mt = 0; mt < 2; mt++)
        #pragma unroll
        for (int nt = 0; nt < 8; nt++)
            #pragma unroll
            for (int j = 0; j < 4; j++) acc[mt][nt][j] = 0.f;

    issue_tile(sb, 0, 0, A0h, A0l, K0, A1h, A1l, K1, Wh, Wl, Kt, mbase, nbase, tid);
    CPCOMMIT();
    if (nk > 1)
        issue_tile(sb, 1, 1, A0h, A0l, K0, A1h, A1l, K1, Wh, Wl, Kt, mbase, nbase, tid);
    CPCOMMIT();

    for (int kt = 0; kt < nk; kt++) {
        int stage = kt % 3;
        CPWAIT1();
        __syncthreads();
        uint32_t base = sb + stage * STAGE_B;
        #pragma unroll
        for (int s = 0; s < 2; s++) {
            uint32_t ca = ((uint32_t)(s * 2 + hi) ^ xr_a) * 16;
            uint32_t cb = ((uint32_t)(s * 2) + b_ch ^ xr_b) * 16;
            uint32_t ah[2][4], al[2][4];
            #pragma unroll
            for (int mt = 0; mt < 2; mt++) {
                uint32_t ad = base + a_ro[mt] + ca;
                LDSM4(ah[mt][0], ah[mt][1], ah[mt][2], ah[mt][3], ad);
                LDSM4(al[mt][0], al[mt][1], al[mt][2], al[mt][3], ad + TILE_B);
            }
            uint32_t bh[8][2], bl[8][2];
            #pragma unroll
            for (int g = 0; g < 4; g++) {
                uint32_t bd = base + 2 * TILE_B + b_ro + g * 1024 + cb;
                uint32_t r0, r1, r2, r3;
                LDSM4(r0, r1, r2, r3, bd);
                bh[g * 2][0] = r0; bh[g * 2][1] = r1;
                bh[g * 2 + 1][0] = r2; bh[g * 2 + 1][1] = r3;
                LDSM4(r0, r1, r2, r3, bd + TILE_B);
                bl[g * 2][0] = r0; bl[g * 2][1] = r1;
                bl[g * 2 + 1][0] = r2; bl[g * 2 + 1][1] = r3;
            }
            #pragma unroll
            for (int mt = 0; mt < 2; mt++)
                #pragma unroll
                for (int nt = 0; nt < 8; nt++) {
                    MMA16816(acc[mt][nt], ah[mt], bh[nt][0], bh[nt][1]);
                    MMA16816(acc[mt][nt], ah[mt], bl[nt][0], bl[nt][1]);
                    MMA16816(acc[mt][nt], al[mt], bh[nt][0], bh[nt][1]);
                }
        }
        if (kt + 2 < nk)
            issue_tile(sb, (kt + 2) % 3, kt + 2, A0h, A0l, K0, A1h, A1l, K1,
                       Wh, Wl, Kt, mbase, nbase, tid);
        CPCOMMIT();
    }

    #pragma unroll
    for (int mt = 0; mt < 2; mt++) {
        int r0 = mbase + wm * 32 + mt * 16 + (lane >> 2);
        int r1 = r0 + 8;
        float ci0 = 0.f, cb0 = 0.f, cc0 = 0.f, inv0 = 1.f;
        float ci1 = 0.f, cb1 = 0.f, cc1 = 0.f, inv1 = 1.f;
        if (mode == 2) {
            if (r0 < N_INTn) {
                ci0 = g_cntI[r0]; cb0 = g_cntB[r0]; cc0 = g_cntC[r0];
                inv0 = 1.f / fmaxf(ci0 + cb0 + cc0, 1.f);
            }
            if (r1 < N_INTn) {
                ci1 = g_cntI[r1]; cb1 = g_cntB[r1]; cc1 = g_cntC[r1];
                inv1 = 1.f / fmaxf(ci1 + cb1 + cc1, 1.f);
            }
        }
        #pragma unroll
        for (int nt = 0; nt < 8; nt++) {
            int nl = wn * 64 + nt * 8 + (lane & 3) * 2;
            float v00 = acc[mt][nt][0], v01 = acc[mt][nt][1];
            float v10 = acc[mt][nt][2], v11 = acc[mt][nt][3];
            if (mode == 0) {
                float b0 = bs1[nl], b1v = bs1[nl + 1];
                if (r0 < M) {
                    float2 o = {v00 + b0, v01 + b1v};
                    *reinterpret_cast<float2*>(C + (size_t)r0 * ldc + nbase + nl) = o;
                }
                if (r1 < M) {
                    float2 o = {v10 + b0, v11 + b1v};
                    *reinterpret_cast<float2*>(C + (size_t)r1 * ldc + nbase + nl) = o;
                }
            } else if (mode == 1) {
                float b0 = bs1[nl], b1v = bs1[nl + 1];
                v00 += b0; v01 += b1v; v10 += b0; v11 += b1v;
                size_t i0 = (size_t)r0 * 128 + nbase + nl;
                size_t i1 = (size_t)r1 * 128 + nbase + nl;
                *reinterpret_cast<uint32_t*>(Dh + i0) = pack_bf2(v00, v01);
                *reinterpret_cast<uint32_t*>(Dl + i0) = pack_lo2(v00, v01);
                *reinterpret_cast<uint32_t*>(Dh + i1) = pack_bf2(v10, v11);
                *reinterpret_cast<uint32_t*>(Dl + i1) = pack_lo2(v10, v11);
            } else {
                float e0 = bs1[nl] , e1 = bs1[nl + 1];
                float f0 = bs2[nl] , f1 = bs2[nl + 1];
                float g0 = bs3[nl] , g1 = bs3[nl + 1];
                v00 = (v00 + ci0 * e0 + cb0 * f0 + cc0 * g0) * inv0;
                v01 = (v01 + ci0 * e1 + cb0 * f1 + cc0 * g1) * inv0;
                v10 = (v10 + ci1 * e0 + cb1 * f0 + cc1 * g0) * inv1;
                v11 = (v11 + ci1 * e1 + cb1 * f1 + cc1 * g1) * inv1;
                size_t i0 = (size_t)r0 * 128 + nbase + nl;
                size_t i1 = (size_t)r1 * 128 + nbase + nl;
                *reinterpret_cast<uint32_t*>(Dh + i0) = pack_bf2(v00, v01);
                *reinterpret_cast<uint32_t*>(Dl + i0) = pack_lo2(v00, v01);
                *reinterpret_cast<uint32_t*>(Dh + i1) = pack_bf2(v10, v11);
                *reinterpret_cast<uint32_t*>(Dl + i1) = pack_lo2(v10, v11);
            }
        }
    }
}

// ---------------- tiny zero (counters only) ----------------
__global__ void k_zero() {
    int idx = blockIdx.x * blockDim.x + threadIdx.x;
    if (idx < N_INTn) {
        g_cntIi[idx] = 0; g_cntBi[idx] = 0; g_cntCi[idx] = 0;
    }
    if (idx == 0) { g_ovfc = 0; g_ovfcB = 0; g_ovfcC = 0; }
}

// ---------------- bucket ALL edge types ----------------
constexpr int E_TOT = E_INTn + E_Bn + E_Cn;

__global__ void k_reorder(const int* __restrict__ eiI, const int* __restrict__ eiB,
                          const int* __restrict__ eiC) {
    int idx = blockIdx.x * blockDim.x + threadIdx.x;
    if (idx < E_INTn) {
        int s = eiI[idx];
        int t = eiI[E_INTn + idx];
        int p = atomicAdd(&g_cntIi[t], 1);
        if (p < MAXD) g_csr[(size_t)t * MAXD + p] = s;
        else { int o = atomicAdd(&g_ovfc, 1); g_ovf[o] = make_int2(s, t); }
        return;
    }
    idx -= E_INTn;
    if (idx < E_Bn) {
        int t = eiB[E_Bn + idx];
        int p = atomicAdd(&g_cntBi[t], 1);
        if (p < MAXB) g_csrB[(size_t)t * MAXB + p] = idx;
        else { int o = atomicAdd(&g_ovfcB, 1); g_ovfB[o] = make_int2(idx, t); }
        return;
    }
    idx -= E_Bn;
    if (idx < E_Cn) {
        int t = eiC[E_Cn + idx];
        int p = atomicAdd(&g_cntCi[t], 1);
        if (p < MAXC) g_csrC[(size_t)t * MAXC + p] = idx;
        else { int o = atomicAdd(&g_ovfcC, 1); g_ovfC[o] = make_int2(idx, t); }
        return;
    }
}

// ---------------- interior gather: aggS + ci*x planes ----------------
__global__ void k_gather(const float* __restrict__ x) {
    int n = (blockIdx.x * blockDim.x + threadIdx.x) >> 5;
    int lane = threadIdx.x & 31;
    if (n >= NP_I) return;
    size_t pb = (size_t)n * KFE + lane * 4;
    if (n >= N_INTn) {
        uint2 z = {0u, 0u};
        *(uint2*)(g_feh + pb) = z;       *(uint2*)(g_fel + pb) = z;
        *(uint2*)(g_feh + pb + 320) = z; *(uint2*)(g_fel + pb + 320) = z;
        return;
    }
    int deg = g_cntIi[n];
    int d = min(deg, MAXD);
    const int* cs = g_csr + (size_t)n * MAXD;
    float4 acc = {0.f, 0.f, 0.f, 0.f};
    int e = 0;
    for (; e + 4 <= d; e += 4) {
        int s0 = cs[e], s1 = cs[e + 1], s2 = cs[e + 2], s3 = cs[e + 3];
        float4 v0 = ((const float4*)(x + (size_t)s0 * D))[lane];
        float4 v1 = ((const float4*)(x + (size_t)s1 * D))[lane];
        float4 v2 = ((const float4*)(x + (size_t)s2 * D))[lane];
        float4 v3 = ((const float4*)(x + (size_t)s3 * D))[lane];
        acc.x += v0.x + v1.x + v2.x + v3.x;
        acc.y += v0.y + v1.y + v2.y + v3.y;
        acc.z += v0.z + v1.z + v2.z + v3.z;
        acc.w += v0.w + v1.w + v2.w + v3.w;
    }
    for (; e < d; e++) {
        int s = cs[e];
        float4 v = ((const float4*)(x + (size_t)s * D))[lane];
        acc.x += v.x; acc.y += v.y; acc.z += v.z; acc.w += v.w;
    }
    if (deg > MAXD) {
        int no = g_ovfc;
        for (int o = 0; o < no; o++) {
            int2 p = g_ovf[o];
            if (p.y == n) {
                float4 v = ((const float4*)(x + (size_t)p.x * D))[lane];
                acc.x += v.x; acc.y += v.y; acc.z += v.z; acc.w += v.w;
            }
        }
    }
    float av[4] = {acc.x, acc.y, acc.z, acc.w};
    uint2 H, L;
    split4(av, H, L);
    *(uint2*)(g_feh + pb) = H;
    *(uint2*)(g_fel + pb) = L;
    float ci = (float)deg;
    float4 xv = ((const float4*)(x + (size_t)n * D))[lane];
    float sv[4] = {ci * xv.x, ci * xv.y, ci * xv.z, ci * xv.w};
    split4(sv, H, L);
    *(uint2*)(g_feh + pb + 320) = H;
    *(uint2*)(g_fel + pb + 320) = L;
    if (lane == 0) g_cntI[n] = ci;
}

// ---------------- B/C gather: aggB/aggC + cb*x/cc*x planes + counts ----------------
__global__ void k_gatherBC(const float* __restrict__ x, const float* __restrict__ xb,
                           const float* __restrict__ u) {
    int n = (blockIdx.x * blockDim.x + threadIdx.x) >> 5;
    int lane = threadIdx.x & 31;
    if (n >= NP_I) return;
    size_t pb = (size_t)n * KFE + lane * 4;
    if (n >= N_INTn) {
        uint2 z = {0u, 0u};
        *(uint2*)(g_feh + pb + 128) = z; *(uint2*)(g_fel + pb + 128) = z;
        if (lane < 16) { *(uint2*)(g_feh + pb + 256) = z; *(uint2*)(g_fel + pb + 256) = z; }
        *(uint2*)(g_feh + pb + 448) = z; *(uint2*)(g_fel + pb + 448) = z;
        *(uint2*)(g_feh + pb + 576) = z; *(uint2*)(g_fel + pb + 576) = z;
        return;
    }
    int degB = g_cntBi[n];
    int degC = g_cntCi[n];
    // aggB (cols [128,256))
    {
        int d = min(degB, MAXB);
        const int* cs = g_csrB + (size_t)n * MAXB;
        float4 acc = {0.f, 0.f, 0.f, 0.f};
        for (int e = 0; e < d; e++) {
            int ed = cs[e];
            float4 v = ((const float4*)(xb + (size_t)ed * D))[lane];
            acc.x += v.x; acc.y += v.y; acc.z += v.z; acc.w += v.w;
        }
        if (degB > MAXB) {
            int no = g_ovfcB;
            for (int o = 0; o < no; o++) {
                int2 p = g_ovfB[o];
                if (p.y == n) {
                    float4 v = ((const float4*)(xb + (size_t)p.x * D))[lane];
                    acc.x += v.x; acc.y += v.y; acc.z += v.z; acc.w += v.w;
                }
            }
        }
        float av[4] = {acc.x, acc.y, acc.z, acc.w};
        uint2 H, L;
        split4(av, H, L);
        *(uint2*)(g_feh + pb + 128) = H;
        *(uint2*)(g_fel + pb + 128) = L;
    }
    // aggC (cols [256,320), lanes < 16)
    if (lane < 16) {
        int d = min(degC, MAXC);
        const int* cs = g_csrC + (size_t)n * MAXC;
        float4 acc = {0.f, 0.f, 0.f, 0.f};
        for (int e = 0; e < d; e++) {
            int ed = cs[e];
            float4 v = ((const float4*)(u + (size_t)ed * DCn))[lane];
            acc.x += v.x; acc.y += v.y; acc.z += v.z; acc.w += v.w;
        }
        if (degC > MAXC) {
            int no = g_ovfcC;
            for (int o = 0; o < no; o++) {
                int2 p = g_ovfC[o];
                if (p.y == n) {
                    float4 v = ((const float4*)(u + (size_t)p.x * DCn))[lane];
                    acc.x += v.x; acc.y += v.y; acc.z += v.z; acc.w += v.w;
                }
            }
        }
        float av[4] = {acc.x, acc.y, acc.z, acc.w};
        uint2 H, L;
        split4(av, H, L);
        *(uint2*)(g_feh + pb + 256) = H;
        *(uint2*)(g_fel + pb + 256) = L;
    }
    // cb*x (cols [448,576)), cc*x (cols [576,704))
    float cb = (float)degB, cc = (float)degC;
    float4 xv = ((const float4*)(x + (size_t)n * D))[lane];
    float sv[4] = {cb * xv.x, cb * xv.y, cb * xv.z, cb * xv.w};
    uint2 H, L;
    split4(sv, H, L);
    *(uint2*)(g_feh + pb + 448) = H;
    *(uint2*)(g_fel + pb + 448) = L;
    float tv[4] = {cc * xv.x, cc * xv.y, cc * xv.z, cc * xv.w};
    split4(tv, H, L);
    *(uint2*)(g_feh + pb + 576) = H;
    *(uint2*)(g_fel + pb + 576) = L;
    if (lane == 0) { g_cntB[n] = cb; g_cntC[n] = cc; }
}

// ---------------- prep_rest: vectorized (unchanged) ----------------
constexpr int V_W1  = 128 * 88;
constexpr int V_WOI = V_W1 + 256 * 32;
constexpr int V_WB1 = V_WOI + 128 * 16;
constexpr int V_WOB = V_WB1 + 256 * 32;
constexpr int V_WC1 = V_WOB + 128 * 8;
constexpr int V_WOC = V_WC1 + 256 * 24;
constexpr int V_B   = V_WOC + 96;
constexpr int V_X   = V_B + NP_I * 16;
constexpr int V_XB  = V_X + NP_B * 16;
constexpr int V_U   = V_XB + NP_C * 8;

__global__ void k_prep_rest(
    const float* __restrict__ x, const float* __restrict__ xb, const float* __restrict__ u,
    const float* __restrict__ Wii, const float* __restrict__ Wbi, const float* __restrict__ Wci,
    const float* __restrict__ Wbb, const float* __restrict__ Wcc,
    const float* __restrict__ Wis, const float* __restrict__ Wim,
    const float* __restrict__ Wbs, const float* __restrict__ Wbm,
    const float* __restrict__ Wcs, const float* __restrict__ Wcm,
    const float* __restrict__ bis, const float* __restrict__ bim,
    const float* __restrict__ bbs, const float* __restrict__ bbm,
    const float* __restrict__ bcs, const float* __restrict__ bcm)
{
    int idx = blockIdx.x * blockDim.x + threadIdx.x;
    float v[8];
    uint4 H, L;
    if (idx < V_W1) {
        int j = idx / 88, k0 = (idx % 88) * 8;
        const float* src;
        if (k0 < 128)      src = Wii + j * 256 + k0;
        else if (k0 < 256) src = Wbi + j * 256 + (k0 - 128);
        else if (k0 < 320) src = Wci + j * 192 + (k0 - 256);
        else if (k0 < 448) src = Wii + j * 256 + 128 + (k0 - 320);
        else if (k0 < 576) src = Wbi + j * 256 + 128 + (k0 - 448);
        else               src = Wci + j * 192 + 64 + (k0 - 576);
        ld8(src, v);
        split8(v, H, L);
        size_t o = (size_t)j * KFE + k0;
        *(uint4*)(g_W1h + o) = H; *(uint4*)(g_W1l + o) = L;
        return;
    }
    if (idx < V_WOI) {
        int i = idx - V_W1;
        int j = i / 32, k0 = (i % 32) * 8;
        const float* src = (k0 < 128) ? Wis + j * 128 + k0 : Wim + j * 128 + (k0 - 128);
        ld8(src, v); split8(v, H, L);
        size_t o = (size_t)j * 256 + k0;
        *(uint4*)(g_WOIh + o) = H; *(uint4*)(g_WOIl + o) = L;
        return;
    }
    if (idx < V_WB1) {
        int i = idx - V_WOI;
        int j = i / 16, k0 = (i % 16) * 8;
        float a[8], b[8];
        ld8(Wbb + j * 256 + k0, a); ld8(Wbb + j * 256 + 128 + k0, b);
        for (int t = 0; t < 8; t++) v[t] = a[t] + b[t];
        split8(v, H, L);
        size_t o = (size_t)j * 128 + k0;
        *(uint4*)(g_WB1h + o) = H; *(uint4*)(g_WB1l + o) = L;
        return;
    }
    if (idx < V_WOB) {
        int i = idx - V_WB1;
        int j = i / 32, k0 = (i % 32) * 8;
        const float* src = (k0 < 128) ? Wbs + j * 128 + k0 : Wbm + j * 128 + (k0 - 128);
        ld8(src, v); split8(v, H, L);
        size_t o = (size_t)j * 256 + k0;
        *(uint4*)(g_WOBh + o) = H; *(uint4*)(g_WOBl + o) = L;
        return;
    }
    if (idx < V_WC1) {
        int i = idx - V_WOB;
        int j = i / 8, k0 = (i % 8) * 8;
        float a[8], b[8];
        ld8(Wcc + j * 128 + k0, a); ld8(Wcc + j * 128 + 64 + k0, b);
        for (int t = 0; t < 8; t++) v[t] = a[t] + b[t];
        split8(v, H, L);
        size_t o = (size_t)j * 64 + k0;
        *(uint4*)(g_WC1h + o) = H; *(uint4*)(g_WC1l + o) = L;
        return;
    }
    if (idx < V_WOC) {
        int i = idx - V_WC1;
        int j = i / 24, k0 = (i % 24) * 8;
        const float* src = (k0 < 64) ? Wcs + j * 64 + k0 : Wcm + j * 128 + (k0 - 64);
        ld8(src, v); split8(v, H, L);
        size_t o = (size_t)j * 192 + k0;
        *(uint4*)(g_WOCh + o) = H; *(uint4*)(g_WOCl + o) = L;
        return;
    }
    if (idx < V_B) {
        int i = idx - V_WOC;
        int which = i / 32, c0 = (i % 32) * 8;
        const float *a, *b;
        float* dst;
        if (which == 0) { a = bis; b = bim; dst = g_bOI; }
        else if (which == 1) { a = bbs; b = bbm; dst = g_bOB; }
        else { a = bcs; b = bcm; dst = g_bOC; }
        float av[8], bv[8];
        ld8(a + c0, av); ld8(b + c0, bv);
        float4 o0, o1;
        o0.x = av[0] + bv[0]; o0.y = av[1] + bv[1]; o0.z = av[2] + bv[2]; o0.w = av[3] + bv[3];
        o1.x = av[4] + bv[4]; o1.y = av[5] + bv[5]; o1.z = av[6] + bv[6]; o1.w = av[7] + bv[7];
        ((float4*)(dst + c0))[0] = o0; ((float4*)(dst + c0))[1] = o1;
        return;
    }
    if (idx < V_X) {
        int i = idx - V_B;
        int m = i >> 4, c8 = (i & 15) * 8;
        if (m < N_INTn) ld8(x + (size_t)m * 128 + c8, v);
        else zero8(v);
        split8(v, H, L);
        size_t o = (size_t)m * 128 + c8;
        *(uint4*)(g_xh + o) = H; *(uint4*)(g_xl + o) = L;
        return;
    }
    if (idx < V_XB) {
        int i = idx - V_X;
        int m = i >> 4, c8 = (i & 15) * 8;
        if (m < E_Bn) ld8(xb + (size_t)m * 128 + c8, v);
        else zero8(v);
        split8(v, H, L);
        size_t o = (size_t)m * 128 + c8;
        *(uint4*)(g_xbh + o) = H; *(uint4*)(g_xbl + o) = L;
        return;
    }
    if (idx < V_U) {
        int i = idx - V_XB;
        int m = i >> 3, c8 = (i & 7) * 8;
        if (m < E_Cn) ld8(u + (size_t)m * 64 + c8, v);
        else zero8(v);
        split8(v, H, L);
        size_t o = (size_t)m * 64 + c8;
        *(uint4*)(g_uh + o) = H; *(uint4*)(g_ul + o) = L;
        return;
    }
}

// ---------------- launch ----------------
static void* symv(const void* s) { void* p = nullptr; cudaGetSymbolAddress(&p, s); return p; }

extern "C" void kernel_launch(void* const* d_in, const int* in_sizes, int n_in,
                              void* d_out, int out_size) {
    const float* x   = (const float*)d_in[0];
    const float* xb  = (const float*)d_in[1];
    const float* u   = (const float*)d_in[2];
    const int*   eiI = (const int*)d_in[3];
    const int*   eiB = (const int*)d_in[4];
    const int*   eiC = (const int*)d_in[5];
    const float* Wii = (const float*)d_in[8];
    const float* bii = (const float*)d_in[9];
    const float* Wbi = (const float*)d_in[10];
    const float* bbi = (const float*)d_in[11];
    const float* Wci = (const float*)d_in[12];
    const float* bci = (const float*)d_in[13];
    const float* Wbb = (const float*)d_in[14];
    const float* bbb = (const float*)d_in[15];
    const float* Wcc = (const float*)d_in[16];
    const float* bcc = (const float*)d_in[17];
    const float* Wim = (const float*)d_in[18];
    const float* bim = (const float*)d_in[19];
    const float* Wis = (const float*)d_in[20];
    const float* bis = (const float*)d_in[21];
    const float* Wbm = (const float*)d_in[22];
    const float* bbm = (const float*)d_in[23];
    const float* Wbs = (const float*)d_in[24];
    const float* bbs = (const float*)d_in[25];
    const float* Wcm = (const float*)d_in[26];
    const float* bcm = (const float*)d_in[27];
    const float* Wcs = (const float*)d_in[28];
    const float* bcs = (const float*)d_in[29];
    float* out = (float*)d_out;

    auto bfp = [](const void* s) { return (const __nv_bfloat16*)symv(s); };
    auto bfw = [](const void* s) { return (__nv_bfloat16*)symv(s); };

    const __nv_bfloat16 *pxh = bfp(g_xh), *pxl = bfp(g_xl);
    const __nv_bfloat16 *pxbh = bfp(g_xbh), *pxbl = bfp(g_xbl);
    const __nv_bfloat16 *puh = bfp(g_uh), *pul = bfp(g_ul);
    const __nv_bfloat16 *pfeh = bfp(g_feh), *pfel = bfp(g_fel);
    __nv_bfloat16 *paggh = bfw(g_aggh), *paggl = bfw(g_aggl);
    __nv_bfloat16 *psbh = bfw(g_sbh), *psbl = bfw(g_sbl);
    __nv_bfloat16 *psch = bfw(g_sch), *pscl = bfw(g_scl);
    const __nv_bfloat16 *pW1h = bfp(g_W1h), *pW1l = bfp(g_W1l);
    const __nv_bfloat16 *pWOIh = bfp(g_WOIh), *pWOIl = bfp(g_WOIl);
    const __nv_bfloat16 *pWB1h = bfp(g_WB1h), *pWB1l = bfp(g_WB1l);
    const __nv_bfloat16 *pWOBh = bfp(g_WOBh), *pWOBl = bfp(g_WOBl);
    const __nv_bfloat16 *pWC1h = bfp(g_WC1h), *pWC1l = bfp(g_WC1l);
    const __nv_bfloat16 *pWOCh = bfp(g_WOCh), *pWOCl = bfp(g_WOCl);
    const float *pbOI = (const float*)symv(g_bOI);
    const float *pbOB = (const float*)symv(g_bOB);
    const float *pbOC = (const float*)symv(g_bOC);

    static cudaStream_t s1 = nullptr;
    static cudaEvent_t evF = nullptr, evR = nullptr, evJ = nullptr;
    if (s1 == nullptr) {
        cudaStreamCreateWithFlags(&s1, cudaStreamNonBlocking);
        cudaEventCreateWithFlags(&evF, cudaEventDisableTiming);
        cudaEventCreateWithFlags(&evR, cudaEventDisableTiming);
        cudaEventCreateWithFlags(&evJ, cudaEventDisableTiming);
        cudaFuncSetAttribute(k_gemm, cudaFuncAttributeMaxDynamicSharedMemorySize, SM_TOT);
    }

    // fork
    cudaEventRecord(evF, 0);
    cudaStreamWaitEvent(s1, evF, 0);

    // ---- s1: fully scatter-independent ----
    k_prep_rest<<<(V_U + 255) / 256, 256, 0, s1>>>(
        x, xb, u, Wii, Wbi, Wci, Wbb, Wcc, Wis, Wim, Wbs, Wbm, Wcs, Wcm,
        bis, bim, bbs, bbm, bcs, bcm);
    cudaEventRecord(evR, s1);
    // SB = xb @ WB1^T + bbb -> planes
    k_gemm<<<dim3(157, 1), 256, SM_TOT, s1>>>(
        pxbh, pxbl, 128, nullptr, nullptr, 0, pWB1h, pWB1l,
        bbb, nullptr, 0, 0, psbh, psbl, 1, nullptr, nullptr, nullptr);
    // OUT-B = [xb | SB] @ WOB^T + bOB
    k_gemm<<<dim3(157, 2), 256, SM_TOT, s1>>>(
        pxbh, pxbl, 128, psbh, psbl, 128, pWOBh, pWOBl,
        pbOB, out + (size_t)N_INTn * 256, 256, E_Bn, nullptr, nullptr, 0,
        nullptr, nullptr, nullptr);
    // SC = u @ WC1^T + bcc -> planes
    k_gemm<<<dim3(79, 1), 256, SM_TOT, s1>>>(
        puh, pul, 64, nullptr, nullptr, 0, pWC1h, pWC1l,
        bcc, nullptr, 0, 0, psch, pscl, 1, nullptr, nullptr, nullptr);
    // OUT-C = [u | SC] @ WOC^T + bOC
    k_gemm<<<dim3(79, 2), 256, SM_TOT, s1>>>(
        puh, pul, 64, psch, pscl, 128, pWOCh, pWOCl,
        pbOC, out + (size_t)(N_INTn + E_Bn) * 256, 256, E_Cn, nullptr, nullptr, 0,
        nullptr, nullptr, nullptr);
    cudaEventRecord(evJ, s1);

    // ---- s0: interior + B/C gather chain ----
    k_zero<<<(N_INTn + 255) / 256, 256>>>();
    k_reorder<<<(E_TOT + 255) / 256, 256>>>(eiI, eiB, eiC);
    k_gather<<<(NP_I * 32 + 255) / 256, 256>>>(x);
    k_gatherBC<<<(NP_I * 32 + 255) / 256, 256>>>(x, xb, u);

    cudaStreamWaitEvent(0, evR, 0);   // W1 planes ready
    // AGG = featext @ W1ext^T (K=704); epilogue: counts + msg biases -> planes
    k_gemm<<<dim3(391, 1), 256, SM_TOT>>>(
        pfeh, pfel, KFE, nullptr, nullptr, 0, pW1h, pW1l,
        nullptr, nullptr, 0, 0, paggh, paggl, 2, bii, bbi, bci);
    // OUT-I = [x | AGG] @ WOI^T + bOI
    k_gemm<<<dim3(391, 2), 256, SM_TOT>>>(
        pxh, pxl, 128, paggh, paggl, 128, pWOIh, pWOIl,
        pbOI, out, 256, N_INTn, nullptr, nullptr, 0, nullptr, nullptr, nullptr);

    // join
    cudaStreamWaitEvent(0, evJ, 0);
}

// round 17
// speedup vs baseline: 1.1202x; 1.0825x over previous
#include <cuda_runtime.h>
#include <cuda_bf16.h>
#include <cstdint>
#include <cstddef>

// ---------------- problem constants ----------------
constexpr int N_INTn = 50000;
constexpr int D      = 128;
constexpr int DCn    = 64;
constexpr int E_INTn = 500000;
constexpr int E_Bn   = 20000;
constexpr int E_Cn   = 10000;
constexpr int NP_I   = 50048;   // 391*128
constexpr int NP_B   = 20096;   // 157*128
constexpr int NP_C   = 10112;   // 79*128
constexpr int KFE    = 704;     // featext K
constexpr int MAXD   = 64;      // interior CSR slots per node
constexpr int MAXB   = 16;      // boundary CSR slots per node
constexpr int MAXC   = 16;      // control CSR slots per node
constexpr int NBLK_I = 391;

// ---------------- scratch ----------------
__device__ float g_cntI[N_INTn], g_cntB[N_INTn], g_cntC[N_INTn];
__device__ int   g_cntIi[N_INTn], g_cntBi[N_INTn], g_cntCi[N_INTn];
__device__ int   g_csr[(size_t)N_INTn * MAXD];
__device__ int   g_csrB[(size_t)N_INTn * MAXB];
__device__ int   g_csrC[(size_t)N_INTn * MAXC];
__device__ int   g_ovfc, g_ovfcB, g_ovfcC;
__device__ int2  g_ovf[E_INTn];
__device__ int2  g_ovfB[E_Bn];
__device__ int2  g_ovfC[E_Cn];
__device__ float g_bOI[256], g_bOB[256], g_bOC[256];
__device__ int   g_flag[NBLK_I];

// ---------------- bf16 hi/lo planes ----------------
__device__ __align__(16) __nv_bfloat16 g_xh[NP_I * 128],  g_xl[NP_I * 128];
__device__ __align__(16) __nv_bfloat16 g_xbh[NP_B * 128], g_xbl[NP_B * 128];
__device__ __align__(16) __nv_bfloat16 g_uh[NP_C * 64],   g_ul[NP_C * 64];
__device__ __align__(16) __nv_bfloat16 g_feh[(size_t)NP_I * KFE], g_fel[(size_t)NP_I * KFE];
__device__ __align__(16) __nv_bfloat16 g_aggh[NP_I * 128], g_aggl[NP_I * 128];
__device__ __align__(16) __nv_bfloat16 g_sbh[NP_B * 128],  g_sbl[NP_B * 128];
__device__ __align__(16) __nv_bfloat16 g_sch[NP_C * 128],  g_scl[NP_C * 128];
// weight planes
__device__ __align__(16) __nv_bfloat16 g_W1h[128 * KFE], g_W1l[128 * KFE];
__device__ __align__(16) __nv_bfloat16 g_WOIh[256 * 256], g_WOIl[256 * 256];
__device__ __align__(16) __nv_bfloat16 g_WB1h[128 * 128], g_WB1l[128 * 128];
__device__ __align__(16) __nv_bfloat16 g_WOBh[256 * 256], g_WOBl[256 * 256];
__device__ __align__(16) __nv_bfloat16 g_WC1h[128 * 64],  g_WC1l[128 * 64];
__device__ __align__(16) __nv_bfloat16 g_WOCh[256 * 192], g_WOCl[256 * 192];

// ---------------- PTX helpers ----------------
__device__ __forceinline__ uint32_t cvta_s(const void* p) {
    uint32_t a;
    asm("{ .reg .u64 t; cvta.to.shared.u64 t, %1; cvt.u32.u64 %0, t; }" : "=r"(a) : "l"(p));
    return a;
}
#define CPA16(dst, src) asm volatile("cp.async.cg.shared.global [%0], [%1], 16;" :: "r"(dst), "l"(src))
#define CPCOMMIT()      asm volatile("cp.async.commit_group;" ::: "memory")
#define CPWAIT1()       asm volatile("cp.async.wait_group 1;" ::: "memory")

#define LDSM4(r0, r1, r2, r3, a) \
    asm volatile("ldmatrix.sync.aligned.m8n8.x4.shared.b16 {%0,%1,%2,%3}, [%4];" \
                 : "=r"(r0), "=r"(r1), "=r"(r2), "=r"(r3) : "r"(a))

#define MMA16816(c, av, b0, b1) \
    asm volatile("mma.sync.aligned.m16n8k16.row.col.f32.bf16.bf16.f32 " \
                 "{%0,%1,%2,%3}, {%4,%5,%6,%7}, {%8,%9}, {%0,%1,%2,%3};" \
                 : "+f"((c)[0]), "+f"((c)[1]), "+f"((c)[2]), "+f"((c)[3]) \
                 : "r"((av)[0]), "r"((av)[1]), "r"((av)[2]), "r"((av)[3]), \
                   "r"(b0), "r"(b1))

__device__ __forceinline__ uint32_t pack_bf2(float a, float b) {
    __nv_bfloat162 t;
    t.x = __float2bfloat16_rn(a);
    t.y = __float2bfloat16_rn(b);
    return *reinterpret_cast<uint32_t*>(&t);
}
__device__ __forceinline__ uint32_t pack_lo2(float a, float b) {
    __nv_bfloat16 ha = __float2bfloat16_rn(a), hb = __float2bfloat16_rn(b);
    __nv_bfloat162 t;
    t.x = __float2bfloat16_rn(a - __bfloat162float(ha));
    t.y = __float2bfloat16_rn(b - __bfloat162float(hb));
    return *reinterpret_cast<uint32_t*>(&t);
}
__device__ __forceinline__ void split8(const float* v, uint4& H, uint4& L) {
    __nv_bfloat16 h[8], l[8];
    #pragma unroll
    for (int j = 0; j < 8; j++) {
        h[j] = __float2bfloat16_rn(v[j]);
        l[j] = __float2bfloat16_rn(v[j] - __bfloat162float(h[j]));
    }
    H = *reinterpret_cast<const uint4*>(h);
    L = *reinterpret_cast<const uint4*>(l);
}
__device__ __forceinline__ void split4(const float* v, uint2& H, uint2& L) {
    __nv_bfloat16 h[4], l[4];
    for (int j = 0; j < 4; j++) {
        h[j] = __float2bfloat16_rn(v[j]);
        l[j] = __float2bfloat16_rn(v[j] - __bfloat162float(h[j]));
    }
    H = *reinterpret_cast<const uint2*>(h);
    L = *reinterpret_cast<const uint2*>(l);
}
__device__ __forceinline__ void ld8(const float* p, float* v) {
    float4 a = ((const float4*)p)[0], b = ((const float4*)p)[1];
    v[0]=a.x; v[1]=a.y; v[2]=a.z; v[3]=a.w; v[4]=b.x; v[5]=b.y; v[6]=b.z; v[7]=b.w;
}
__device__ __forceinline__ void zero8(float* v) {
    for (int j = 0; j < 8; j++) v[j] = 0.f;
}

// ---------------- generic plane GEMM core ----------------
constexpr int TILE_B  = 128 * 64;
constexpr int STAGE_B = 4 * TILE_B;
constexpr int SM_BIAS = 3 * STAGE_B;
constexpr int SM_TOT  = SM_BIAS + 3 * 128 * 4;

__device__ __forceinline__ void issue_tile(
    uint32_t sb, int stage, int kt,
    const __nv_bfloat16* A0h, const __nv_bfloat16* A0l, int K0,
    const __nv_bfloat16* A1h, const __nv_bfloat16* A1l, int K1,
    const __nv_bfloat16* Wh, const __nv_bfloat16* Wl, int Kt,
    int mbase, int nbase, int tid)
{
    int kc = kt << 5;
    const __nv_bfloat16 *ah, *al;
    int ld, ko;
    if (kc < K0) { ah = A0h; al = A0l; ld = K0; ko = kc; }
    else         { ah = A1h; al = A1l; ld = K1; ko = kc - K0; }
    uint32_t base = sb + stage * STAGE_B;
    #pragma unroll
    for (int r = 0; r < 2; r++) {
        int chunk = tid + r * 256;
        int row = chunk >> 2, c = chunk & 3;
        uint32_t sc = (uint32_t)(c ^ ((row >> 1) & 3));
        uint32_t off = row * 64 + sc * 16;
        size_t aoff = (size_t)(mbase + row) * ld + ko + c * 8;
        size_t woff = (size_t)(nbase + row) * Kt + kc + c * 8;
        CPA16(base + off,              ah + aoff);
        CPA16(base + TILE_B + off,     al + aoff);
        CPA16(base + 2 * TILE_B + off, Wh + woff);
        CPA16(base + 3 * TILE_B + off, Wl + woff);
    }
}

// mode 0: fp32 out C = acc + bias; mode 1: split planes (+bias); mode 2: AGG epilogue
// wf: spin on *wf before consuming A1 tiles (first two tile prefetches are A0-only).
// sf: after epilogue, fence + set *sf = 1.
__device__ __forceinline__ void gemm_core(
    const __nv_bfloat16* __restrict__ A0h, const __nv_bfloat16* __restrict__ A0l, int K0,
    const __nv_bfloat16* __restrict__ A1h, const __nv_bfloat16* __restrict__ A1l, int K1,
    const __nv_bfloat16* __restrict__ Wh,  const __nv_bfloat16* __restrict__ Wl,
    const float* __restrict__ bias,
    float* __restrict__ C, int ldc, int M,
    __nv_bfloat16* __restrict__ Dh, __nv_bfloat16* __restrict__ Dl,
    int mode,
    const float* __restrict__ b1, const float* __restrict__ b2,
    const float* __restrict__ b3,
    int mbase, int nbase,
    const int* wf, int* sf,
    char* smem)
{
    uint32_t sb = cvta_s(smem);
    const int tid  = threadIdx.x;
    const int wid  = tid >> 5;
    const int lane = tid & 31;
    const int wm   = wid >> 1;
    const int wn   = wid & 1;
    const int Kt = K0 + K1;
    const int nk = Kt >> 5;

    float* bs1 = (float*)(smem + SM_BIAS);
    float* bs2 = bs1 + 128;
    float* bs3 = bs2 + 128;
    if (tid < 128) {
        if (mode == 2) {
            bs1[tid] = b1[tid]; bs2[tid] = b2[tid]; bs3[tid] = b3[tid];
        } else {
            bs1[tid] = bias ? bias[nbase + tid] : 0.f;
        }
    }

    const int hi = lane >> 4;
    const int jj = lane >> 3;
    const int a_row0 = wm * 32 + (lane & 15);
    const uint32_t xr_a = (uint32_t)((a_row0 >> 1) & 3);
    const uint32_t a_ro[2] = {(uint32_t)(a_row0 * 64), (uint32_t)((a_row0 + 16) * 64)};
    const int b_row0 = wn * 64 + ((jj >> 1) * 8) + (lane & 7);
    const uint32_t xr_b = (uint32_t)((b_row0 >> 1) & 3);
    const uint32_t b_ro = (uint32_t)(b_row0 * 64);
    const uint32_t b_ch = (uint32_t)(jj & 1);

    float acc[2][8][4];
    #pragma unroll
    for (int mt = 0; mt < 2; mt++)
        #pragma unroll
        for (int nt = 0; nt < 8; nt++)
            #pragma unroll
            for (int j = 0; j < 4; j++) acc[mt][nt][j] = 0.f;

    issue_tile(sb, 0, 0, A0h, A0l, K0, A1h, A1l, K1, Wh, Wl, Kt, mbase, nbase, tid);
    CPCOMMIT();
    if (nk > 1)
        issue_tile(sb, 1, 1, A0h, A0l, K0, A1h, A1l, K1, Wh, Wl, Kt, mbase, nbase, tid);
    CPCOMMIT();

    // wait for producer block before touching A1 tiles (tiles 0,1 are A0-only)
    if (wf) {
        if (tid == 0) {
            while (atomicAdd((int*)wf, 0) == 0) { }
        }
        __syncthreads();
    }

    for (int kt = 0; kt < nk; kt++) {
        int stage = kt % 3;
        CPWAIT1();
        __syncthreads();
        uint32_t base = sb + stage * STAGE_B;
        #pragma unroll
        for (int s = 0; s < 2; s++) {
            uint32_t ca = ((uint32_t)(s * 2 + hi) ^ xr_a) * 16;
            uint32_t cb = ((uint32_t)(s * 2) + b_ch ^ xr_b) * 16;
            uint32_t ah[2][4], al[2][4];
            #pragma unroll
            for (int mt = 0; mt < 2; mt++) {
                uint32_t ad = base + a_ro[mt] + ca;
                LDSM4(ah[mt][0], ah[mt][1], ah[mt][2], ah[mt][3], ad);
                LDSM4(al[mt][0], al[mt][1], al[mt][2], al[mt][3], ad + TILE_B);
            }
            uint32_t bh[8][2], bl[8][2];
            #pragma unroll
            for (int g = 0; g < 4; g++) {
                uint32_t bd = base + 2 * TILE_B + b_ro + g * 1024 + cb;
                uint32_t r0, r1, r2, r3;
                LDSM4(r0, r1, r2, r3, bd);
                bh[g * 2][0] = r0; bh[g * 2][1] = r1;
                bh[g * 2 + 1][0] = r2; bh[g * 2 + 1][1] = r3;
                LDSM4(r0, r1, r2, r3, bd + TILE_B);
                bl[g * 2][0] = r0; bl[g * 2][1] = r1;
                bl[g * 2 + 1][0] = r2; bl[g * 2 + 1][1] = r3;
            }
            #pragma unroll
            for (int mt = 0; mt < 2; mt++)
                #pragma unroll
                for (int nt = 0; nt < 8; nt++) {
                    MMA16816(acc[mt][nt], ah[mt], bh[nt][0], bh[nt][1]);
                    MMA16816(acc[mt][nt], ah[mt], bl[nt][0], bl[nt][1]);
                    MMA16816(acc[mt][nt], al[mt], bh[nt][0], bh[nt][1]);
                }
        }
        if (kt + 2 < nk)
            issue_tile(sb, (kt + 2) % 3, kt + 2, A0h, A0l, K0, A1h, A1l, K1,
                       Wh, Wl, Kt, mbase, nbase, tid);
        CPCOMMIT();
    }

    #pragma unroll
    for (int mt = 0; mt < 2; mt++) {
        int r0 = mbase + wm * 32 + mt * 16 + (lane >> 2);
        int r1 = r0 + 8;
        float ci0 = 0.f, cb0 = 0.f, cc0 = 0.f, inv0 = 1.f;
        float ci1 = 0.f, cb1 = 0.f, cc1 = 0.f, inv1 = 1.f;
        if (mode == 2) {
            if (r0 < N_INTn) {
                ci0 = g_cntI[r0]; cb0 = g_cntB[r0]; cc0 = g_cntC[r0];
                inv0 = 1.f / fmaxf(ci0 + cb0 + cc0, 1.f);
            }
            if (r1 < N_INTn) {
                ci1 = g_cntI[r1]; cb1 = g_cntB[r1]; cc1 = g_cntC[r1];
                inv1 = 1.f / fmaxf(ci1 + cb1 + cc1, 1.f);
            }
        }
        #pragma unroll
        for (int nt = 0; nt < 8; nt++) {
            int nl = wn * 64 + nt * 8 + (lane & 3) * 2;
            float v00 = acc[mt][nt][0], v01 = acc[mt][nt][1];
            float v10 = acc[mt][nt][2], v11 = acc[mt][nt][3];
            if (mode == 0) {
                float b0 = bs1[nl], b1v = bs1[nl + 1];
                if (r0 < M) {
                    float2 o = {v00 + b0, v01 + b1v};
                    *reinterpret_cast<float2*>(C + (size_t)r0 * ldc + nbase + nl) = o;
                }
                if (r1 < M) {
                    float2 o = {v10 + b0, v11 + b1v};
                    *reinterpret_cast<float2*>(C + (size_t)r1 * ldc + nbase + nl) = o;
                }
            } else if (mode == 1) {
                float b0 = bs1[nl], b1v = bs1[nl + 1];
                v00 += b0; v01 += b1v; v10 += b0; v11 += b1v;
                size_t i0 = (size_t)r0 * 128 + nbase + nl;
                size_t i1 = (size_t)r1 * 128 + nbase + nl;
                *reinterpret_cast<uint32_t*>(Dh + i0) = pack_bf2(v00, v01);
                *reinterpret_cast<uint32_t*>(Dl + i0) = pack_lo2(v00, v01);
                *reinterpret_cast<uint32_t*>(Dh + i1) = pack_bf2(v10, v11);
                *reinterpret_cast<uint32_t*>(Dl + i1) = pack_lo2(v10, v11);
            } else {
                float e0 = bs1[nl] , e1 = bs1[nl + 1];
                float f0 = bs2[nl] , f1 = bs2[nl + 1];
                float g0 = bs3[nl] , g1 = bs3[nl + 1];
                v00 = (v00 + ci0 * e0 + cb0 * f0 + cc0 * g0) * inv0;
                v01 = (v01 + ci0 * e1 + cb0 * f1 + cc0 * g1) * inv0;
                v10 = (v10 + ci1 * e0 + cb1 * f0 + cc1 * g0) * inv1;
                v11 = (v11 + ci1 * e1 + cb1 * f1 + cc1 * g1) * inv1;
                size_t i0 = (size_t)r0 * 128 + nbase + nl;
                size_t i1 = (size_t)r1 * 128 + nbase + nl;
                *reinterpret_cast<uint32_t*>(Dh + i0) = pack_bf2(v00, v01);
                *reinterpret_cast<uint32_t*>(Dl + i0) = pack_lo2(v00, v01);
                *reinterpret_cast<uint32_t*>(Dh + i1) = pack_bf2(v10, v11);
                *reinterpret_cast<uint32_t*>(Dl + i1) = pack_lo2(v10, v11);
            }
        }
    }

    if (sf) {
        __threadfence();
        __syncthreads();
        if (tid == 0) atomicExch(sf, 1);
    }
}

__global__ void __launch_bounds__(256, 2) k_gemm(
    const __nv_bfloat16* __restrict__ A0h, const __nv_bfloat16* __restrict__ A0l, int K0,
    const __nv_bfloat16* __restrict__ A1h, const __nv_bfloat16* __restrict__ A1l, int K1,
    const __nv_bfloat16* __restrict__ Wh,  const __nv_bfloat16* __restrict__ Wl,
    const float* __restrict__ bias,
    float* __restrict__ C, int ldc, int M,
    __nv_bfloat16* __restrict__ Dh, __nv_bfloat16* __restrict__ Dl,
    int mode,
    const float* __restrict__ b1, const float* __restrict__ b2,
    const float* __restrict__ b3)
{
    extern __shared__ char smem[];
    gemm_core(A0h, A0l, K0, A1h, A1l, K1, Wh, Wl, bias, C, ldc, M, Dh, Dl,
              mode, b1, b2, b3, blockIdx.x * 128, blockIdx.y * 128,
              nullptr, nullptr, smem);
}

// fused AGG (y==0) + OUT-I (y==1,2) with per-block flags
__global__ void __launch_bounds__(256, 2) k_fused(
    const __nv_bfloat16* __restrict__ feh, const __nv_bfloat16* __restrict__ fel,
    const __nv_bfloat16* __restrict__ W1h, const __nv_bfloat16* __restrict__ W1l,
    __nv_bfloat16* __restrict__ aggh, __nv_bfloat16* __restrict__ aggl,
    const float* __restrict__ bii, const float* __restrict__ bbi,
    const float* __restrict__ bci,
    const __nv_bfloat16* __restrict__ xh, const __nv_bfloat16* __restrict__ xl,
    const __nv_bfloat16* __restrict__ WOIh, const __nv_bfloat16* __restrict__ WOIl,
    const float* __restrict__ bOI, float* __restrict__ out)
{
    extern __shared__ char smem[];
    int mb = blockIdx.x;
    if (blockIdx.y == 0) {
        gemm_core(feh, fel, KFE, nullptr, nullptr, 0, W1h, W1l,
                  nullptr, nullptr, 0, 0, aggh, aggl,
                  2, bii, bbi, bci, mb * 128, 0,
                  nullptr, &g_flag[mb], smem);
    } else {
        gemm_core(xh, xl, 128, aggh, aggl, 128, WOIh, WOIl,
                  bOI, out, 256, N_INTn, nullptr, nullptr,
                  0, nullptr, nullptr, nullptr, mb * 128, (blockIdx.y - 1) * 128,
                  &g_flag[mb], nullptr, smem);
    }
}

// ---------------- tiny zero (counters + flags) ----------------
__global__ void k_zero() {
    int idx = blockIdx.x * blockDim.x + threadIdx.x;
    if (idx < N_INTn) {
        g_cntIi[idx] = 0; g_cntBi[idx] = 0; g_cntCi[idx] = 0;
    }
    if (idx < NBLK_I) g_flag[idx] = 0;
    if (idx == 0) { g_ovfc = 0; g_ovfcB = 0; g_ovfcC = 0; }
}

// ---------------- bucket ALL edge types ----------------
constexpr int E_TOT = E_INTn + E_Bn + E_Cn;

__global__ void k_reorder(const int* __restrict__ eiI, const int* __restrict__ eiB,
                          const int* __restrict__ eiC) {
    int idx = blockIdx.x * blockDim.x + threadIdx.x;
    if (idx < E_INTn) {
        int s = eiI[idx];
        int t = eiI[E_INTn + idx];
        int p = atomicAdd(&g_cntIi[t], 1);
        if (p < MAXD) g_csr[(size_t)t * MAXD + p] = s;
        else { int o = atomicAdd(&g_ovfc, 1); g_ovf[o] = make_int2(s, t); }
        return;
    }
    idx -= E_INTn;
    if (idx < E_Bn) {
        int t = eiB[E_Bn + idx];
        int p = atomicAdd(&g_cntBi[t], 1);
        if (p < MAXB) g_csrB[(size_t)t * MAXB + p] = idx;
        else { int o = atomicAdd(&g_ovfcB, 1); g_ovfB[o] = make_int2(idx, t); }
        return;
    }
    idx -= E_Bn;
    if (idx < E_Cn) {
        int t = eiC[E_Cn + idx];
        int p = atomicAdd(&g_cntCi[t], 1);
        if (p < MAXC) g_csrC[(size_t)t * MAXC + p] = idx;
        else { int o = atomicAdd(&g_ovfcC, 1); g_ovfC[o] = make_int2(idx, t); }
        return;
    }
}

// ---------------- interior gather: aggS + ci*x planes ----------------
__global__ void k_gather(const float* __restrict__ x) {
    int n = (blockIdx.x * blockDim.x + threadIdx.x) >> 5;
    int lane = threadIdx.x & 31;
    if (n >= NP_I) return;
    size_t pb = (size_t)n * KFE + lane * 4;
    if (n >= N_INTn) {
        uint2 z = {0u, 0u};
        *(uint2*)(g_feh + pb) = z;       *(uint2*)(g_fel + pb) = z;
        *(uint2*)(g_feh + pb + 320) = z; *(uint2*)(g_fel + pb + 320) = z;
        return;
    }
    int deg = g_cntIi[n];
    int d = min(deg, MAXD);
    const int* cs = g_csr + (size_t)n * MAXD;
    float4 acc = {0.f, 0.f, 0.f, 0.f};
    int e = 0;
    for (; e + 4 <= d; e += 4) {
        int s0 = cs[e], s1 = cs[e + 1], s2 = cs[e + 2], s3 = cs[e + 3];
        float4 v0 = ((const float4*)(x + (size_t)s0 * D))[lane];
        float4 v1 = ((const float4*)(x + (size_t)s1 * D))[lane];
        float4 v2 = ((const float4*)(x + (size_t)s2 * D))[lane];
        float4 v3 = ((const float4*)(x + (size_t)s3 * D))[lane];
        acc.x += v0.x + v1.x + v2.x + v3.x;
        acc.y += v0.y + v1.y + v2.y + v3.y;
        acc.z += v0.z + v1.z + v2.z + v3.z;
        acc.w += v0.w + v1.w + v2.w + v3.w;
    }
    for (; e < d; e++) {
        int s = cs[e];
        float4 v = ((const float4*)(x + (size_t)s * D))[lane];
        acc.x += v.x; acc.y += v.y; acc.z += v.z; acc.w += v.w;
    }
    if (deg > MAXD) {
        int no = g_ovfc;
        for (int o = 0; o < no; o++) {
            int2 p = g_ovf[o];
            if (p.y == n) {
                float4 v = ((const float4*)(x + (size_t)p.x * D))[lane];
                acc.x += v.x; acc.y += v.y; acc.z += v.z; acc.w += v.w;
            }
        }
    }
    float av[4] = {acc.x, acc.y, acc.z, acc.w};
    uint2 H, L;
    split4(av, H, L);
    *(uint2*)(g_feh + pb) = H;
    *(uint2*)(g_fel + pb) = L;
    float ci = (float)deg;
    float4 xv = ((const float4*)(x + (size_t)n * D))[lane];
    float sv[4] = {ci * xv.x, ci * xv.y, ci * xv.z, ci * xv.w};
    split4(sv, H, L);
    *(uint2*)(g_feh + pb + 320) = H;
    *(uint2*)(g_fel + pb + 320) = L;
    if (lane == 0) g_cntI[n] = ci;
}

// ---------------- B/C gather: aggB/aggC + cb*x/cc*x planes + counts ----------------
__global__ void k_gatherBC(const float* __restrict__ x, const float* __restrict__ xb,
                           const float* __restrict__ u) {
    int n = (blockIdx.x * blockDim.x + threadIdx.x) >> 5;
    int lane = threadIdx.x & 31;
    if (n >= NP_I) return;
    size_t pb = (size_t)n * KFE + lane * 4;
    if (n >= N_INTn) {
        uint2 z = {0u, 0u};
        *(uint2*)(g_feh + pb + 128) = z; *(uint2*)(g_fel + pb + 128) = z;
        if (lane < 16) { *(uint2*)(g_feh + pb + 256) = z; *(uint2*)(g_fel + pb + 256) = z; }
        *(uint2*)(g_feh + pb + 448) = z; *(uint2*)(g_fel + pb + 448) = z;
        *(uint2*)(g_feh + pb + 576) = z; *(uint2*)(g_fel + pb + 576) = z;
        return;
    }
    int degB = g_cntBi[n];
    int degC = g_cntCi[n];
    {
        int d = min(degB, MAXB);
        const int* cs = g_csrB + (size_t)n * MAXB;
        float4 acc = {0.f, 0.f, 0.f, 0.f};
        for (int e = 0; e < d; e++) {
            int ed = cs[e];
            float4 v = ((const float4*)(xb + (size_t)ed * D))[lane];
            acc.x += v.x; acc.y += v.y; acc.z += v.z; acc.w += v.w;
        }
        if (degB > MAXB) {
            int no = g_ovfcB;
            for (int o = 0; o < no; o++) {
                int2 p = g_ovfB[o];
                if (p.y == n) {
                    float4 v = ((const float4*)(xb + (size_t)p.x * D))[lane];
                    acc.x += v.x; acc.y += v.y; acc.z += v.z; acc.w += v.w;
                }
            }
        }
        float av[4] = {acc.x, acc.y, acc.z, acc.w};
        uint2 H, L;
        split4(av, H, L);
        *(uint2*)(g_feh + pb + 128) = H;
        *(uint2*)(g_fel + pb + 128) = L;
    }
    if (lane < 16) {
        int d = min(degC, MAXC);
        const int* cs = g_csrC + (size_t)n * MAXC;
        float4 acc = {0.f, 0.f, 0.f, 0.f};
        for (int e = 0; e < d; e++) {
            int ed = cs[e];
            float4 v = ((const float4*)(u + (size_t)ed * DCn))[lane];
            acc.x += v.x; acc.y += v.y; acc.z += v.z; acc.w += v.w;
        }
        if (degC > MAXC) {
            int no = g_ovfcC;
            for (int o = 0; o < no; o++) {
                int2 p = g_ovfC[o];
                if (p.y == n) {
                    float4 v = ((const float4*)(u + (size_t)p.x * DCn))[lane];
                    acc.x += v.x; acc.y += v.y; acc.z += v.z; acc.w += v.w;
                }
            }
        }
        float av[4] = {acc.x, acc.y, acc.z, acc.w};
        uint2 H, L;
        split4(av, H, L);
        *(uint2*)(g_feh + pb + 256) = H;
        *(uint2*)(g_fel + pb + 256) = L;
    }
    float cb = (float)degB, cc = (float)degC;
    float4 xv = ((const float4*)(x + (size_t)n * D))[lane];
    float sv[4] = {cb * xv.x, cb * xv.y, cb * xv.z, cb * xv.w};
    uint2 H, L;
    split4(sv, H, L);
    *(uint2*)(g_feh + pb + 448) = H;
    *(uint2*)(g_fel + pb + 448) = L;
    float tv[4] = {cc * xv.x, cc * xv.y, cc * xv.z, cc * xv.w};
    split4(tv, H, L);
    *(uint2*)(g_feh + pb + 576) = H;
    *(uint2*)(g_fel + pb + 576) = L;
    if (lane == 0) { g_cntB[n] = cb; g_cntC[n] = cc; }
}

// ---------------- prep_rest: vectorized (unchanged) ----------------
constexpr int V_W1  = 128 * 88;
constexpr int V_WOI = V_W1 + 256 * 32;
constexpr int V_WB1 = V_WOI + 128 * 16;
constexpr int V_WOB = V_WB1 + 256 * 32;
constexpr int V_WC1 = V_WOB + 128 * 8;
constexpr int V_WOC = V_WC1 + 256 * 24;
constexpr int V_B   = V_WOC + 96;
constexpr int V_X   = V_B + NP_I * 16;
constexpr int V_XB  = V_X + NP_B * 16;
constexpr int V_U   = V_XB + NP_C * 8;

__global__ void k_prep_rest(
    const float* __restrict__ x, const float* __restrict__ xb, const float* __restrict__ u,
    const float* __restrict__ Wii, const float* __restrict__ Wbi, const float* __restrict__ Wci,
    const float* __restrict__ Wbb, const float* __restrict__ Wcc,
    const float* __restrict__ Wis, const float* __restrict__ Wim,
    const float* __restrict__ Wbs, const float* __restrict__ Wbm,
    const float* __restrict__ Wcs, const float* __restrict__ Wcm,
    const float* __restrict__ bis, const float* __restrict__ bim,
    const float* __restrict__ bbs, const float* __restrict__ bbm,
    const float* __restrict__ bcs, const float* __restrict__ bcm)
{
    int idx = blockIdx.x * blockDim.x + threadIdx.x;
    float v[8];
    uint4 H, L;
    if (idx < V_W1) {
        int j = idx / 88, k0 = (idx % 88) * 8;
        const float* src;
        if (k0 < 128)      src = Wii + j * 256 + k0;
        else if (k0 < 256) src = Wbi + j * 256 + (k0 - 128);
        else if (k0 < 320) src = Wci + j * 192 + (k0 - 256);
        else if (k0 < 448) src = Wii + j * 256 + 128 + (k0 - 320);
        else if (k0 < 576) src = Wbi + j * 256 + 128 + (k0 - 448);
        else               src = Wci + j * 192 + 64 + (k0 - 576);
        ld8(src, v);
        split8(v, H, L);
        size_t o = (size_t)j * KFE + k0;
        *(uint4*)(g_W1h + o) = H; *(uint4*)(g_W1l + o) = L;
        return;
    }
    if (idx < V_WOI) {
        int i = idx - V_W1;
        int j = i / 32, k0 = (i % 32) * 8;
        const float* src = (k0 < 128) ? Wis + j * 128 + k0 : Wim + j * 128 + (k0 - 128);
        ld8(src, v); split8(v, H, L);
        size_t o = (size_t)j * 256 + k0;
        *(uint4*)(g_WOIh + o) = H; *(uint4*)(g_WOIl + o) = L;
        return;
    }
    if (idx < V_WB1) {
        int i = idx - V_WOI;
        int j = i / 16, k0 = (i % 16) * 8;
        float a[8], b[8];
        ld8(Wbb + j * 256 + k0, a); ld8(Wbb + j * 256 + 128 + k0, b);
        for (int t = 0; t < 8; t++) v[t] = a[t] + b[t];
        split8(v, H, L);
        size_t o = (size_t)j * 128 + k0;
        *(uint4*)(g_WB1h + o) = H; *(uint4*)(g_WB1l + o) = L;
        return;
    }
    if (idx < V_WOB) {
        int i = idx - V_WB1;
        int j = i / 32, k0 = (i % 32) * 8;
        const float* src = (k0 < 128) ? Wbs + j * 128 + k0 : Wbm + j * 128 + (k0 - 128);
        ld8(src, v); split8(v, H, L);
        size_t o = (size_t)j * 256 + k0;
        *(uint4*)(g_WOBh + o) = H; *(uint4*)(g_WOBl + o) = L;
        return;
    }
    if (idx < V_WC1) {
        int i = idx - V_WOB;
        int j = i / 8, k0 = (i % 8) * 8;
        float a[8], b[8];
        ld8(Wcc + j * 128 + k0, a); ld8(Wcc + j * 128 + 64 + k0, b);
        for (int t = 0; t < 8; t++) v[t] = a[t] + b[t];
        split8(v, H, L);
        size_t o = (size_t)j * 64 + k0;
        *(uint4*)(g_WC1h + o) = H; *(uint4*)(g_WC1l + o) = L;
        return;
    }
    if (idx < V_WOC) {
        int i = idx - V_WC1;
        int j = i / 24, k0 = (i % 24) * 8;
        const float* src = (k0 < 64) ? Wcs + j * 64 + k0 : Wcm + j * 128 + (k0 - 64);
        ld8(src, v); split8(v, H, L);
        size_t o = (size_t)j * 192 + k0;
        *(uint4*)(g_WOCh + o) = H; *(uint4*)(g_WOCl + o) = L;
        return;
    }
    if (idx < V_B) {
        int i = idx - V_WOC;
        int which = i / 32, c0 = (i % 32) * 8;
        const float *a, *b;
        float* dst;
        if (which == 0) { a = bis; b = bim; dst = g_bOI; }
        else if (which == 1) { a = bbs; b = bbm; dst = g_bOB; }
        else { a = bcs; b = bcm; dst = g_bOC; }
        float av[8], bv[8];
        ld8(a + c0, av); ld8(b + c0, bv);
        float4 o0, o1;
        o0.x = av[0] + bv[0]; o0.y = av[1] + bv[1]; o0.z = av[2] + bv[2]; o0.w = av[3] + bv[3];
        o1.x = av[4] + bv[4]; o1.y = av[5] + bv[5]; o1.z = av[6] + bv[6]; o1.w = av[7] + bv[7];
        ((float4*)(dst + c0))[0] = o0; ((float4*)(dst + c0))[1] = o1;
        return;
    }
    if (idx < V_X) {
        int i = idx - V_B;
        int m = i >> 4, c8 = (i & 15) * 8;
        if (m < N_INTn) ld8(x + (size_t)m * 128 + c8, v);
        else zero8(v);
        split8(v, H, L);
        size_t o = (size_t)m * 128 + c8;
        *(uint4*)(g_xh + o) = H; *(uint4*)(g_xl + o) = L;
        return;
    }
    if (idx < V_XB) {
        int i = idx - V_X;
        int m = i >> 4, c8 = (i & 15) * 8;
        if (m < E_Bn) ld8(xb + (size_t)m * 128 + c8, v);
        else zero8(v);
        split8(v, H, L);
        size_t o = (size_t)m * 128 + c8;
        *(uint4*)(g_xbh + o) = H; *(uint4*)(g_xbl + o) = L;
        return;
    }
    if (idx < V_U) {
        int i = idx - V_XB;
        int m = i >> 3, c8 = (i & 7) * 8;
        if (m < E_Cn) ld8(u + (size_t)m * 64 + c8, v);
        else zero8(v);
        split8(v, H, L);
        size_t o = (size_t)m * 64 + c8;
        *(uint4*)(g_uh + o) = H; *(uint4*)(g_ul + o) = L;
        return;
    }
}

// ---------------- launch ----------------
static void* symv(const void* s) { void* p = nullptr; cudaGetSymbolAddress(&p, s); return p; }

extern "C" void kernel_launch(void* const* d_in, const int* in_sizes, int n_in,
                              void* d_out, int out_size) {
    const float* x   = (const float*)d_in[0];
    const float* xb  = (const float*)d_in[1];
    const float* u   = (const float*)d_in[2];
    const int*   eiI = (const int*)d_in[3];
    const int*   eiB = (const int*)d_in[4];
    const int*   eiC = (const int*)d_in[5];
    const float* Wii = (const float*)d_in[8];
    const float* bii = (const float*)d_in[9];
    const float* Wbi = (const float*)d_in[10];
    const float* bbi = (const float*)d_in[11];
    const float* Wci = (const float*)d_in[12];
    const float* bci = (const float*)d_in[13];
    const float* Wbb = (const float*)d_in[14];
    const float* bbb = (const float*)d_in[15];
    const float* Wcc = (const float*)d_in[16];
    const float* bcc = (const float*)d_in[17];
    const float* Wim = (const float*)d_in[18];
    const float* bim = (const float*)d_in[19];
    const float* Wis = (const float*)d_in[20];
    const float* bis = (const float*)d_in[21];
    const float* Wbm = (const float*)d_in[22];
    const float* bbm = (const float*)d_in[23];
    const float* Wbs = (const float*)d_in[24];
    const float* bbs = (const float*)d_in[25];
    const float* Wcm = (const float*)d_in[26];
    const float* bcm = (const float*)d_in[27];
    const float* Wcs = (const float*)d_in[28];
    const float* bcs = (const float*)d_in[29];
    float* out = (float*)d_out;

    auto bfp = [](const void* s) { return (const __nv_bfloat16*)symv(s); };
    auto bfw = [](const void* s) { return (__nv_bfloat16*)symv(s); };

    const __nv_bfloat16 *pxh = bfp(g_xh), *pxl = bfp(g_xl);
    const __nv_bfloat16 *pxbh = bfp(g_xbh), *pxbl = bfp(g_xbl);
    const __nv_bfloat16 *puh = bfp(g_uh), *pul = bfp(g_ul);
    const __nv_bfloat16 *pfeh = bfp(g_feh), *pfel = bfp(g_fel);
    __nv_bfloat16 *paggh = bfw(g_aggh), *paggl = bfw(g_aggl);
    __nv_bfloat16 *psbh = bfw(g_sbh), *psbl = bfw(g_sbl);
    __nv_bfloat16 *psch = bfw(g_sch), *pscl = bfw(g_scl);
    const __nv_bfloat16 *pW1h = bfp(g_W1h), *pW1l = bfp(g_W1l);
    const __nv_bfloat16 *pWOIh = bfp(g_WOIh), *pWOIl = bfp(g_WOIl);
    const __nv_bfloat16 *pWB1h = bfp(g_WB1h), *pWB1l = bfp(g_WB1l);
    const __nv_bfloat16 *pWOBh = bfp(g_WOBh), *pWOBl = bfp(g_WOBl);
    const __nv_bfloat16 *pWC1h = bfp(g_WC1h), *pWC1l = bfp(g_WC1l);
    const __nv_bfloat16 *pWOCh = bfp(g_WOCh), *pWOCl = bfp(g_WOCl);
    const float *pbOI = (const float*)symv(g_bOI);
    const float *pbOB = (const float*)symv(g_bOB);
    const float *pbOC = (const float*)symv(g_bOC);

    static cudaStream_t s1 = nullptr;
    static cudaEvent_t evF = nullptr, evR = nullptr, evJ = nullptr;
    if (s1 == nullptr) {
        cudaStreamCreateWithFlags(&s1, cudaStreamNonBlocking);
        cudaEventCreateWithFlags(&evF, cudaEventDisableTiming);
        cudaEventCreateWithFlags(&evR, cudaEventDisableTiming);
        cudaEventCreateWithFlags(&evJ, cudaEventDisableTiming);
        cudaFuncSetAttribute(k_gemm, cudaFuncAttributeMaxDynamicSharedMemorySize, SM_TOT);
        cudaFuncSetAttribute(k_fused, cudaFuncAttributeMaxDynamicSharedMemorySize, SM_TOT);
    }

    // fork
    cudaEventRecord(evF, 0);
    cudaStreamWaitEvent(s1, evF, 0);

    // ---- s1: fully scatter-independent ----
    k_prep_rest<<<(V_U + 255) / 256, 256, 0, s1>>>(
        x, xb, u, Wii, Wbi, Wci, Wbb, Wcc, Wis, Wim, Wbs, Wbm, Wcs, Wcm,
        bis, bim, bbs, bbm, bcs, bcm);
    cudaEventRecord(evR, s1);
    k_gemm<<<dim3(157, 1), 256, SM_TOT, s1>>>(
        pxbh, pxbl, 128, nullptr, nullptr, 0, pWB1h, pWB1l,
        bbb, nullptr, 0, 0, psbh, psbl, 1, nullptr, nullptr, nullptr);
    k_gemm<<<dim3(157, 2), 256, SM_TOT, s1>>>(
        pxbh, pxbl, 128, psbh, psbl, 128, pWOBh, pWOBl,
        pbOB, out + (size_t)N_INTn * 256, 256, E_Bn, nullptr, nullptr, 0,
        nullptr, nullptr, nullptr);
    k_gemm<<<dim3(79, 1), 256, SM_TOT, s1>>>(
        puh, pul, 64, nullptr, nullptr, 0, pWC1h, pWC1l,
        bcc, nullptr, 0, 0, psch, pscl, 1, nullptr, nullptr, nullptr);
    k_gemm<<<dim3(79, 2), 256, SM_TOT, s1>>>(
        puh, pul, 64, psch, pscl, 128, pWOCh, pWOCl,
        pbOC, out + (size_t)(N_INTn + E_Bn) * 256, 256, E_Cn, nullptr, nullptr, 0,
        nullptr, nullptr, nullptr);
    cudaEventRecord(evJ, s1);

    // ---- s0: interior chain ----
    k_zero<<<(N_INTn + 255) / 256, 256>>>();
    k_reorder<<<(E_TOT + 255) / 256, 256>>>(eiI, eiB, eiC);
    k_gather<<<(NP_I * 32 + 255) / 256, 256>>>(x);
    k_gatherBC<<<(NP_I * 32 + 255) / 256, 256>>>(x, xb, u);

    cudaStreamWaitEvent(0, evR, 0);   // W1/WOI/x planes ready
    // fused AGG + OUT-I with per-block flag pipelining
    k_fused<<<dim3(NBLK_I, 3), 256, SM_TOT>>>(
        pfeh, pfel, pW1h, pW1l, paggh, paggl, bii, bbi, bci,
        pxh, pxl, pWOIh, pWOIl, pbOI, out);

    // join
    cudaStreamWaitEvent(0, evJ, 0);
}